// round 2
// baseline (speedup 1.0000x reference)
#include <cuda_runtime.h>

// ---------------------------------------------------------------------------
// MultiHeadAttention: B=2, S=2048, D=1024, H=16, HD=64, causal.
//   y = O-proj( softmax( (XqWq^T)(XkWk^T)^T * 1/8, causal ) (XvWv^T) )
// Round 0/1: fp32 SIMT baseline with packed fma.rn.f32x2 (FFMA2) inner loops.
// (Round 1 re-run: round 0/1 benches died on broker infra, no data yet.)
// ---------------------------------------------------------------------------

constexpr int BB   = 2;
constexpr int SEQ  = 2048;
constexpr int DIM  = 1024;
constexpr int NH   = 16;
constexpr int HDIM = 64;
constexpr int MTOT = BB * SEQ;          // 4096 rows for projection GEMMs
constexpr float SCALE = 0.125f;         // 1/sqrt(64)

constexpr int BM = 64, BN = 64, BK = 16;
constexpr int ASTR = 68;                                   // attn smem row stride (floats)
constexpr int ATTN_SMEM_BYTES = 4 * 64 * ASTR * (int)sizeof(float);  // 69632

// Scratch (allocation-free rule: __device__ globals).
__device__ float g_qh[(size_t)BB * NH * SEQ * HDIM];   // [b,h,s,hd]
__device__ float g_kh[(size_t)BB * NH * SEQ * HDIM];
__device__ float g_vh[(size_t)BB * NH * SEQ * HDIM];
__device__ float g_ao[(size_t)BB * SEQ * DIM];         // [b,s,d] merged heads

// ---- packed f32x2 helpers (FFMA2 path; ptxas won't auto-fuse from C++) ----
__device__ __forceinline__ unsigned long long pack2(float lo, float hi) {
    unsigned long long d;
    asm("mov.b64 %0, {%1, %2};" : "=l"(d)
        : "r"(__float_as_uint(lo)), "r"(__float_as_uint(hi)));
    return d;
}
__device__ __forceinline__ void fma2(unsigned long long& d,
                                     unsigned long long a, unsigned long long b) {
    asm("fma.rn.f32x2 %0, %1, %2, %0;" : "+l"(d) : "l"(a), "l"(b));
}
__device__ __forceinline__ void mul2(unsigned long long& d, unsigned long long a) {
    asm("mul.rn.f32x2 %0, %0, %1;" : "+l"(d) : "l"(a));
}
__device__ __forceinline__ float2 unpack2(unsigned long long d) {
    unsigned lo, hi;
    asm("mov.b64 {%0, %1}, %2;" : "=r"(lo), "=r"(hi) : "l"(d));
    return make_float2(__uint_as_float(lo), __uint_as_float(hi));
}

// ---------------------------------------------------------------------------
// Projection GEMM: Y[m][e] = sum_k X[m][k] * W[e][k] + bias[e]
// mode 0/1/2: X = q/k/v input, output scattered to g_qh/g_kh/g_vh [b,h,s,hd]
// mode 3:     X = g_ao, output dense to Yout (d_out) [b,s,d]
// 64x64x16 tile, 256 threads, 4x4 per thread, f32x2 accumulation.
// ---------------------------------------------------------------------------
__global__ __launch_bounds__(256) void proj_kernel(
    const float* __restrict__ Xin, const float* __restrict__ W,
    const float* __restrict__ bias, float* __restrict__ Yout, int mode)
{
    __shared__ __align__(16) float As[BK][BM + 4];  // [k][m], transposed on load
    __shared__ __align__(16) float Bs[BK][BN + 4];  // [k][e], transposed on load

    const float* X = (mode == 3) ? g_ao : Xin;

    const int tid = threadIdx.x;
    const int tx  = tid & 15;
    const int ty  = tid >> 4;
    const int n0  = blockIdx.x * BN;
    const int m0  = blockIdx.y * BM;
    const int lr  = tid >> 2;          // 0..63 tile row
    const int lk  = (tid & 3) << 2;    // 0,4,8,12 k offset

    unsigned long long acc[4][2] = {};

    const float* xp = X + (size_t)(m0 + lr) * DIM + lk;
    const float* wp = W + (size_t)(n0 + lr) * DIM + lk;

    for (int kb = 0; kb < DIM; kb += BK) {
        float4 xa = *(const float4*)(xp + kb);
        float4 wb = *(const float4*)(wp + kb);
        As[lk + 0][lr] = xa.x; As[lk + 1][lr] = xa.y;
        As[lk + 2][lr] = xa.z; As[lk + 3][lr] = xa.w;
        Bs[lk + 0][lr] = wb.x; Bs[lk + 1][lr] = wb.y;
        Bs[lk + 2][lr] = wb.z; Bs[lk + 3][lr] = wb.w;
        __syncthreads();
#pragma unroll
        for (int k = 0; k < BK; k++) {
            float4 a = *(const float4*)(&As[k][ty << 2]);
            ulonglong2 b = *(const ulonglong2*)(&Bs[k][tx << 2]);
            float av[4] = {a.x, a.y, a.z, a.w};
#pragma unroll
            for (int i = 0; i < 4; i++) {
                unsigned long long a2 = pack2(av[i], av[i]);
                fma2(acc[i][0], a2, b.x);
                fma2(acc[i][1], a2, b.y);
            }
        }
        __syncthreads();
    }

    const int e0 = n0 + (tx << 2);
    float4 bv4 = *(const float4*)(bias + e0);

#pragma unroll
    for (int i = 0; i < 4; i++) {
        float2 p0 = unpack2(acc[i][0]);
        float2 p1 = unpack2(acc[i][1]);
        float4 r = make_float4(p0.x + bv4.x, p0.y + bv4.y,
                               p1.x + bv4.z, p1.y + bv4.w);
        int m = m0 + (ty << 2) + i;
        if (mode == 3) {
            *(float4*)(Yout + (size_t)m * DIM + e0) = r;
        } else {
            int b  = m >> 11;           // m / SEQ
            int s  = m & (SEQ - 1);
            int h  = e0 >> 6;           // e / HDIM (constant over the 4 cols)
            int hd = e0 & 63;
            float* dst = (mode == 0) ? g_qh : (mode == 1) ? g_kh : g_vh;
            *(float4*)(dst + (((size_t)(b * NH + h) * SEQ) + s) * HDIM + hd) = r;
        }
    }
}

// ---------------------------------------------------------------------------
// Flash attention: one block per (bh, 64-query tile). 256 threads, 4x4/thread.
// Online softmax, causal. Q pre-scaled by 1/8. K tiles iterate 0..qt.
// ---------------------------------------------------------------------------
__global__ __launch_bounds__(256) void attn_kernel()
{
    extern __shared__ __align__(16) float sm[];
    float* Qt = sm;                 // [k(hd)][qrow]  transposed, pre-scaled
    float* Kt = sm + 64 * ASTR;     // [k(hd)][kvrow] transposed
    float* Vs = sm + 2 * 64 * ASTR; // [kvrow][hd]    natural
    float* Ps = sm + 3 * 64 * ASTR; // [qrow][kvrow]  natural

    const int tid = threadIdx.x;
    const int tx  = tid & 15;
    const int ty  = tid >> 4;
    const int qt  = blockIdx.x;     // query tile 0..31
    const int bh  = blockIdx.y;     // batch*head 0..31

    const int lr = tid >> 2;        // 0..63
    const int lk = (tid & 3) << 2;  // 0,4,8,12

    const size_t base = (size_t)bh * SEQ;

    // Load Q tile -> transposed smem, folding in the 1/sqrt(HD) scale.
    {
        const float* qp = g_qh + (base + (size_t)qt * 64 + lr) * HDIM;
#pragma unroll
        for (int c = 0; c < 4; c++) {
            int col = lk + c * 16;
            float4 qv = *(const float4*)(qp + col);
            Qt[(col + 0) * ASTR + lr] = qv.x * SCALE;
            Qt[(col + 1) * ASTR + lr] = qv.y * SCALE;
            Qt[(col + 2) * ASTR + lr] = qv.z * SCALE;
            Qt[(col + 3) * ASTR + lr] = qv.w * SCALE;
        }
    }

    float m_i[4], l_i[4];
    unsigned long long o2[4][2] = {};
#pragma unroll
    for (int i = 0; i < 4; i++) { m_i[i] = -1e30f; l_i[i] = 0.f; }

    for (int kt = 0; kt <= qt; kt++) {
        __syncthreads();  // prev PV done (and Q store visible on first iter)
        {
            const float* kp = g_kh + (base + (size_t)kt * 64 + lr) * HDIM;
            const float* vp = g_vh + (base + (size_t)kt * 64 + lr) * HDIM;
#pragma unroll
            for (int c = 0; c < 4; c++) {
                int col = lk + c * 16;
                float4 kv = *(const float4*)(kp + col);
                Kt[(col + 0) * ASTR + lr] = kv.x;
                Kt[(col + 1) * ASTR + lr] = kv.y;
                Kt[(col + 2) * ASTR + lr] = kv.z;
                Kt[(col + 3) * ASTR + lr] = kv.w;
                *(float4*)(Vs + lr * ASTR + col) = *(const float4*)(vp + col);
            }
        }
        __syncthreads();

        // S = (Q*scale) K^T, 4x4 per thread, f32x2
        unsigned long long s2[4][2] = {};
#pragma unroll 4
        for (int k = 0; k < 64; k++) {
            float4 a = *(const float4*)(Qt + k * ASTR + (ty << 2));
            ulonglong2 b = *(const ulonglong2*)(Kt + k * ASTR + (tx << 2));
            float av[4] = {a.x, a.y, a.z, a.w};
#pragma unroll
            for (int i = 0; i < 4; i++) {
                unsigned long long a2 = pack2(av[i], av[i]);
                fma2(s2[i][0], a2, b.x);
                fma2(s2[i][1], a2, b.y);
            }
        }

        float sv[4][4];
#pragma unroll
        for (int i = 0; i < 4; i++) {
            float2 p0 = unpack2(s2[i][0]);
            float2 p1 = unpack2(s2[i][1]);
            sv[i][0] = p0.x; sv[i][1] = p0.y; sv[i][2] = p1.x; sv[i][3] = p1.y;
        }
        if (kt == qt) {  // causal mask on the diagonal tile
#pragma unroll
            for (int i = 0; i < 4; i++)
#pragma unroll
                for (int j = 0; j < 4; j++)
                    if ((tx << 2) + j > (ty << 2) + i) sv[i][j] = -1e30f;
        }

        // online softmax: rows ty*4+i, reduce over the 16 tx lanes
#pragma unroll
        for (int i = 0; i < 4; i++) {
            float tm = fmaxf(fmaxf(sv[i][0], sv[i][1]), fmaxf(sv[i][2], sv[i][3]));
            tm = fmaxf(tm, __shfl_xor_sync(0xffffffffu, tm, 8));
            tm = fmaxf(tm, __shfl_xor_sync(0xffffffffu, tm, 4));
            tm = fmaxf(tm, __shfl_xor_sync(0xffffffffu, tm, 2));
            tm = fmaxf(tm, __shfl_xor_sync(0xffffffffu, tm, 1));
            float mn  = fmaxf(m_i[i], tm);
            float fac = __expf(m_i[i] - mn);
            m_i[i] = mn;
            float rs = 0.f;
#pragma unroll
            for (int j = 0; j < 4; j++) {
                float p = __expf(sv[i][j] - mn);
                sv[i][j] = p;
                rs += p;
            }
            rs += __shfl_xor_sync(0xffffffffu, rs, 8);
            rs += __shfl_xor_sync(0xffffffffu, rs, 4);
            rs += __shfl_xor_sync(0xffffffffu, rs, 2);
            rs += __shfl_xor_sync(0xffffffffu, rs, 1);
            l_i[i] = l_i[i] * fac + rs;
            unsigned long long f2 = pack2(fac, fac);
            mul2(o2[i][0], f2);
            mul2(o2[i][1], f2);
            *(float4*)(Ps + ((ty << 2) + i) * ASTR + (tx << 2)) =
                make_float4(sv[i][0], sv[i][1], sv[i][2], sv[i][3]);
        }
        __syncthreads();

        // O += P V
#pragma unroll 4
        for (int k = 0; k < 64; k++) {
            ulonglong2 b = *(const ulonglong2*)(Vs + k * ASTR + (tx << 2));
#pragma unroll
            for (int i = 0; i < 4; i++) {
                float a = Ps[((ty << 2) + i) * ASTR + k];
                unsigned long long a2 = pack2(a, a);
                fma2(o2[i][0], a2, b.x);
                fma2(o2[i][1], a2, b.y);
            }
        }
    }

    // epilogue: divide by l, merge heads into g_ao[b, s, h*HD + hd]
    const int b = bh / NH;
    const int h = bh % NH;
#pragma unroll
    for (int i = 0; i < 4; i++) {
        float inv = 1.f / l_i[i];
        float2 p0 = unpack2(o2[i][0]);
        float2 p1 = unpack2(o2[i][1]);
        int srow = qt * 64 + (ty << 2) + i;
        float* dst = g_ao + ((size_t)b * SEQ + srow) * DIM + h * HDIM + (tx << 2);
        *(float4*)dst = make_float4(p0.x * inv, p0.y * inv, p1.x * inv, p1.y * inv);
    }
}

// ---------------------------------------------------------------------------
// inputs: 0=q 1=k 2=v 3=attn_mask(bool, static causal -> hardcoded)
//         4=Wq 5=bq 6=Wk 7=bk 8=Wv 9=bv 10=Wo 11=bo
// ---------------------------------------------------------------------------
extern "C" void kernel_launch(void* const* d_in, const int* in_sizes, int n_in,
                              void* d_out, int out_size)
{
    (void)in_sizes; (void)n_in; (void)out_size;
    const float* q  = (const float*)d_in[0];
    const float* k  = (const float*)d_in[1];
    const float* v  = (const float*)d_in[2];
    const float* Wq = (const float*)d_in[4];
    const float* bq = (const float*)d_in[5];
    const float* Wk = (const float*)d_in[6];
    const float* bk = (const float*)d_in[7];
    const float* Wv = (const float*)d_in[8];
    const float* bv = (const float*)d_in[9];
    const float* Wo = (const float*)d_in[10];
    const float* bo = (const float*)d_in[11];

    dim3 pg(DIM / BN, MTOT / BM);  // (16, 64)
    proj_kernel<<<pg, 256>>>(q, Wq, bq, nullptr, 0);
    proj_kernel<<<pg, 256>>>(k, Wk, bk, nullptr, 1);
    proj_kernel<<<pg, 256>>>(v, Wv, bv, nullptr, 2);

    cudaFuncSetAttribute(attn_kernel, cudaFuncAttributeMaxDynamicSharedMemorySize,
                         ATTN_SMEM_BYTES);
    attn_kernel<<<dim3(SEQ / 64, BB * NH), 256, ATTN_SMEM_BYTES>>>();

    proj_kernel<<<pg, 256>>>(nullptr, Wo, bo, (float*)d_out, 3);
}

// round 8
// speedup vs baseline: 1.3073x; 1.3073x over previous
#include <cuda_runtime.h>
#include <cuda_bf16.h>
#include <cstdint>

// ---------------------------------------------------------------------------
// MultiHeadAttention: B=2, S=2048, D=1024, H=16, HD=64, causal.
// Round 8 (= round 7 retry, infra timeout): tcgen05 unreachable via the
// harness's compute_103 virtual arch, so projections use classic
// mma.sync.m16n8k16 bf16 HMMA (base PTX, sm_80+) with fp32 hi/lo split
// (augmented K=3072: A=[xh,xl,xh], B=[wh,wh,wl]).
// Attention stays SIMT FFMA2 this round.
// ---------------------------------------------------------------------------

constexpr int BB   = 2;
constexpr int SEQ  = 2048;
constexpr int DIM  = 1024;
constexpr int NH   = 16;
constexpr int HDIM = 64;
constexpr int MTOT = BB * SEQ;          // 4096
constexpr float SCALE = 0.125f;

// ---- attention (unchanged from round 2) ----
constexpr int ASTR = 68;
constexpr int ATTN_SMEM_BYTES = 4 * 64 * ASTR * (int)sizeof(float);  // 69632

// ---- mma.sync projection GEMM ----
constexpr int KAUG = 3 * DIM;           // 3072
constexpr int GBM = 128, GBN = 128, GBK = 64;
constexpr int NKB  = KAUG / GBK;        // 48
constexpr int SPAD = 8;                 // bf16 row padding
constexpr int SROW = GBK + SPAD;        // 72 bf16 = 144 B row stride

// Scratch (__device__ globals per allocation-free rule).
__device__ float g_qh[(size_t)BB * NH * SEQ * HDIM];
__device__ float g_kh[(size_t)BB * NH * SEQ * HDIM];
__device__ float g_vh[(size_t)BB * NH * SEQ * HDIM];
__device__ float g_ao[(size_t)BB * SEQ * DIM];
__device__ __align__(16) __nv_bfloat16 g_xaug[(size_t)MTOT * KAUG];  // 25.2 MB
__device__ __align__(16) __nv_bfloat16 g_waug[(size_t)DIM  * KAUG];  //  6.3 MB

// ---- packed f32x2 helpers (attention) ----
__device__ __forceinline__ unsigned long long pack2(float lo, float hi) {
    unsigned long long d;
    asm("mov.b64 %0, {%1, %2};" : "=l"(d)
        : "r"(__float_as_uint(lo)), "r"(__float_as_uint(hi)));
    return d;
}
__device__ __forceinline__ void fma2(unsigned long long& d,
                                     unsigned long long a, unsigned long long b) {
    asm("fma.rn.f32x2 %0, %1, %2, %0;" : "+l"(d) : "l"(a), "l"(b));
}
__device__ __forceinline__ void mul2(unsigned long long& d, unsigned long long a) {
    asm("mul.rn.f32x2 %0, %0, %1;" : "+l"(d) : "l"(a));
}
__device__ __forceinline__ float2 unpack2(unsigned long long d) {
    unsigned lo, hi;
    asm("mov.b64 {%0, %1}, %2;" : "=r"(lo), "=r"(hi) : "l"(d));
    return make_float2(__uint_as_float(lo), __uint_as_float(hi));
}

// ---- mma.sync m16n8k16 bf16 (row.col), fp32 accumulate in-place ----
__device__ __forceinline__ void mma_bf16(float* d, const uint32_t* a,
                                         uint32_t b0, uint32_t b1) {
    asm volatile("mma.sync.aligned.m16n8k16.row.col.f32.bf16.bf16.f32 "
        "{%0,%1,%2,%3}, {%4,%5,%6,%7}, {%8,%9}, {%0,%1,%2,%3};"
        : "+f"(d[0]), "+f"(d[1]), "+f"(d[2]), "+f"(d[3])
        : "r"(a[0]), "r"(a[1]), "r"(a[2]), "r"(a[3]), "r"(b0), "r"(b1));
}

// ============================================================================
// fp32 -> augmented bf16 hi/lo conversion.
//   A (activations): lo_seg=1 -> [xh, xl, xh]
//   B (weights):     lo_seg=2 -> [wh, wh, wl]
// ============================================================================
__global__ __launch_bounds__(256) void conv_aug(const float* __restrict__ Xin,
                                                int which_out, int lo_seg,
                                                int src_is_ao, int ngroups)
{
    int i = blockIdx.x * 256 + threadIdx.x;
    if (i >= ngroups) return;
    const float* X = src_is_ao ? g_ao : Xin;
    __nv_bfloat16* out = which_out ? g_waug : g_xaug;

    int m  = i >> 8;            // 256 groups of 4 per 1024-col row
    int kg = (i & 255) << 2;
    float4 v = *(const float4*)(X + (size_t)m * DIM + kg);

    __nv_bfloat16 h0 = __float2bfloat16(v.x);
    __nv_bfloat16 h1 = __float2bfloat16(v.y);
    __nv_bfloat16 h2 = __float2bfloat16(v.z);
    __nv_bfloat16 h3 = __float2bfloat16(v.w);
    __nv_bfloat16 l0 = __float2bfloat16(v.x - __bfloat162float(h0));
    __nv_bfloat16 l1 = __float2bfloat16(v.y - __bfloat162float(h1));
    __nv_bfloat16 l2 = __float2bfloat16(v.z - __bfloat162float(h2));
    __nv_bfloat16 l3 = __float2bfloat16(v.w - __bfloat162float(h3));

    __nv_bfloat162 hA, hB, lA, lB;
    hA.x = h0; hA.y = h1; hB.x = h2; hB.y = h3;
    lA.x = l0; lA.y = l1; lB.x = l2; lB.y = l3;

    __nv_bfloat16* base = out + (size_t)m * KAUG + kg;
    *(__nv_bfloat162*)(base + 0) = hA;
    *(__nv_bfloat162*)(base + 2) = hB;
    __nv_bfloat162 s1A = (lo_seg == 1) ? lA : hA, s1B = (lo_seg == 1) ? lB : hB;
    __nv_bfloat162 s2A = (lo_seg == 2) ? lA : hA, s2B = (lo_seg == 2) ? lB : hB;
    *(__nv_bfloat162*)(base + DIM + 0)     = s1A;
    *(__nv_bfloat162*)(base + DIM + 2)     = s1B;
    *(__nv_bfloat162*)(base + 2 * DIM + 0) = s2A;
    *(__nv_bfloat162*)(base + 2 * DIM + 2) = s2B;
}

// ============================================================================
// HMMA projection GEMM: Y[m][e] = sum_k g_xaug[m][k] * g_waug[e][k] + bias
// 128x128x64 block, 8 warps (4m x 2n), warp tile 32x64, m16n8k16 atoms.
// mode 0/1/2: scatter to g_qh/g_kh/g_vh [b,h,s,hd];  mode 3: dense to Yout.
// ============================================================================
__global__ __launch_bounds__(256) void gemm_mma(const float* __restrict__ bias,
                                                float* __restrict__ Yout, int mode)
{
    __shared__ __align__(16) __nv_bfloat16 As[GBM][SROW];
    __shared__ __align__(16) __nv_bfloat16 Bs[GBN][SROW];

    const int tid = threadIdx.x;
    const int wid  = tid >> 5;
    const int lane = tid & 31;
    const int wm = wid >> 1;            // 0..3  (32 rows each)
    const int wn = wid & 1;             // 0..1  (64 cols each)
    const int r4 = lane >> 2;           // 0..7
    const int q2 = (lane & 3) << 1;     // 0,2,4,6
    const int n0 = blockIdx.x * GBN;
    const int m0 = blockIdx.y * GBM;

    const int lr = tid >> 1;            // 0..127 tile row for gmem loads
    const int ls = (tid & 1) << 2;      // 0 or 4: uint4 segment base

    float acc[2][8][4] = {};

    const __nv_bfloat16* ag = g_xaug + (size_t)(m0 + lr) * KAUG + ls * 8;
    const __nv_bfloat16* bg = g_waug + (size_t)(n0 + lr) * KAUG + ls * 8;

    for (int kb = 0; kb < NKB; kb++) {
        // load A,B tiles: 128 rows x 64 bf16 (8 uint4/row, 4 per thread-half)
        {
            const __nv_bfloat16* a = ag + kb * GBK;
            const __nv_bfloat16* b = bg + kb * GBK;
#pragma unroll
            for (int j = 0; j < 4; j++) {
                *(uint4*)&As[lr][(ls + j) * 8] = *(const uint4*)(a + j * 8);
                *(uint4*)&Bs[lr][(ls + j) * 8] = *(const uint4*)(b + j * 8);
            }
        }
        __syncthreads();

#pragma unroll
        for (int ka = 0; ka < 4; ka++) {
            const int k0 = ka * 16;
            uint32_t afr[2][4];
#pragma unroll
            for (int ma = 0; ma < 2; ma++) {
                const int R = wm * 32 + ma * 16;
                afr[ma][0] = *(const uint32_t*)&As[R + r4    ][k0 + q2    ];
                afr[ma][1] = *(const uint32_t*)&As[R + r4 + 8][k0 + q2    ];
                afr[ma][2] = *(const uint32_t*)&As[R + r4    ][k0 + q2 + 8];
                afr[ma][3] = *(const uint32_t*)&As[R + r4 + 8][k0 + q2 + 8];
            }
#pragma unroll
            for (int na = 0; na < 8; na++) {
                const int N = wn * 64 + na * 8;
                uint32_t b0 = *(const uint32_t*)&Bs[N + r4][k0 + q2    ];
                uint32_t b1 = *(const uint32_t*)&Bs[N + r4][k0 + q2 + 8];
                mma_bf16(acc[0][na], afr[0], b0, b1);
                mma_bf16(acc[1][na], afr[1], b0, b1);
            }
        }
        __syncthreads();
    }

    // epilogue: bias + scatter/dense store (float2 per accumulator pair)
    float* hdst = (mode == 0) ? g_qh : (mode == 1) ? g_kh : g_vh;
#pragma unroll
    for (int ma = 0; ma < 2; ma++) {
#pragma unroll
        for (int na = 0; na < 8; na++) {
            const int e  = n0 + wn * 64 + na * 8 + q2;
            const float2 bv = *(const float2*)(bias + e);
            const int row0 = m0 + wm * 32 + ma * 16 + r4;
#pragma unroll
            for (int h2i = 0; h2i < 2; h2i++) {
                const int m = row0 + h2i * 8;
                float2 rv = make_float2(acc[ma][na][h2i * 2 + 0] + bv.x,
                                        acc[ma][na][h2i * 2 + 1] + bv.y);
                if (mode == 3) {
                    *(float2*)(Yout + (size_t)m * DIM + e) = rv;
                } else {
                    const int b = m >> 11, s = m & (SEQ - 1);
                    const int h = e >> 6, hd = e & 63;
                    *(float2*)(hdst + (((size_t)(b * NH + h) * SEQ) + s) * HDIM + hd) = rv;
                }
            }
        }
    }
}

// ============================================================================
// Flash attention (unchanged round-2 SIMT FFMA2 version)
// ============================================================================
__global__ __launch_bounds__(256) void attn_kernel()
{
    extern __shared__ __align__(16) float sm[];
    float* Qt = sm;
    float* Kt = sm + 64 * ASTR;
    float* Vs = sm + 2 * 64 * ASTR;
    float* Ps = sm + 3 * 64 * ASTR;

    const int tid = threadIdx.x;
    const int tx  = tid & 15;
    const int ty  = tid >> 4;
    const int qt  = blockIdx.x;
    const int bh  = blockIdx.y;

    const int lr = tid >> 2;
    const int lk = (tid & 3) << 2;

    const size_t base = (size_t)bh * SEQ;

    {
        const float* qp = g_qh + (base + (size_t)qt * 64 + lr) * HDIM;
#pragma unroll
        for (int c = 0; c < 4; c++) {
            int col = lk + c * 16;
            float4 qv = *(const float4*)(qp + col);
            Qt[(col + 0) * ASTR + lr] = qv.x * SCALE;
            Qt[(col + 1) * ASTR + lr] = qv.y * SCALE;
            Qt[(col + 2) * ASTR + lr] = qv.z * SCALE;
            Qt[(col + 3) * ASTR + lr] = qv.w * SCALE;
        }
    }

    float m_i[4], l_i[4];
    unsigned long long o2[4][2] = {};
#pragma unroll
    for (int i = 0; i < 4; i++) { m_i[i] = -1e30f; l_i[i] = 0.f; }

    for (int kt = 0; kt <= qt; kt++) {
        __syncthreads();
        {
            const float* kp = g_kh + (base + (size_t)kt * 64 + lr) * HDIM;
            const float* vp = g_vh + (base + (size_t)kt * 64 + lr) * HDIM;
#pragma unroll
            for (int c = 0; c < 4; c++) {
                int col = lk + c * 16;
                float4 kv = *(const float4*)(kp + col);
                Kt[(col + 0) * ASTR + lr] = kv.x;
                Kt[(col + 1) * ASTR + lr] = kv.y;
                Kt[(col + 2) * ASTR + lr] = kv.z;
                Kt[(col + 3) * ASTR + lr] = kv.w;
                *(float4*)(Vs + lr * ASTR + col) = *(const float4*)(vp + col);
            }
        }
        __syncthreads();

        unsigned long long s2[4][2] = {};
#pragma unroll 4
        for (int k = 0; k < 64; k++) {
            float4 a = *(const float4*)(Qt + k * ASTR + (ty << 2));
            ulonglong2 b = *(const ulonglong2*)(Kt + k * ASTR + (tx << 2));
            float av[4] = {a.x, a.y, a.z, a.w};
#pragma unroll
            for (int i = 0; i < 4; i++) {
                unsigned long long a2 = pack2(av[i], av[i]);
                fma2(s2[i][0], a2, b.x);
                fma2(s2[i][1], a2, b.y);
            }
        }

        float sv[4][4];
#pragma unroll
        for (int i = 0; i < 4; i++) {
            float2 p0 = unpack2(s2[i][0]);
            float2 p1 = unpack2(s2[i][1]);
            sv[i][0] = p0.x; sv[i][1] = p0.y; sv[i][2] = p1.x; sv[i][3] = p1.y;
        }
        if (kt == qt) {
#pragma unroll
            for (int i = 0; i < 4; i++)
#pragma unroll
                for (int j = 0; j < 4; j++)
                    if ((tx << 2) + j > (ty << 2) + i) sv[i][j] = -1e30f;
        }

#pragma unroll
        for (int i = 0; i < 4; i++) {
            float tm = fmaxf(fmaxf(sv[i][0], sv[i][1]), fmaxf(sv[i][2], sv[i][3]));
            tm = fmaxf(tm, __shfl_xor_sync(0xffffffffu, tm, 8));
            tm = fmaxf(tm, __shfl_xor_sync(0xffffffffu, tm, 4));
            tm = fmaxf(tm, __shfl_xor_sync(0xffffffffu, tm, 2));
            tm = fmaxf(tm, __shfl_xor_sync(0xffffffffu, tm, 1));
            float mn  = fmaxf(m_i[i], tm);
            float fac = __expf(m_i[i] - mn);
            m_i[i] = mn;
            float rs = 0.f;
#pragma unroll
            for (int j = 0; j < 4; j++) {
                float p = __expf(sv[i][j] - mn);
                sv[i][j] = p;
                rs += p;
            }
            rs += __shfl_xor_sync(0xffffffffu, rs, 8);
            rs += __shfl_xor_sync(0xffffffffu, rs, 4);
            rs += __shfl_xor_sync(0xffffffffu, rs, 2);
            rs += __shfl_xor_sync(0xffffffffu, rs, 1);
            l_i[i] = l_i[i] * fac + rs;
            unsigned long long f2 = pack2(fac, fac);
            mul2(o2[i][0], f2);
            mul2(o2[i][1], f2);
            *(float4*)(Ps + ((ty << 2) + i) * ASTR + (tx << 2)) =
                make_float4(sv[i][0], sv[i][1], sv[i][2], sv[i][3]);
        }
        __syncthreads();

#pragma unroll 4
        for (int k = 0; k < 64; k++) {
            ulonglong2 b = *(const ulonglong2*)(Vs + k * ASTR + (tx << 2));
#pragma unroll
            for (int i = 0; i < 4; i++) {
                float a = Ps[((ty << 2) + i) * ASTR + k];
                unsigned long long a2 = pack2(a, a);
                fma2(o2[i][0], a2, b.x);
                fma2(o2[i][1], a2, b.y);
            }
        }
    }

    const int b = bh / NH;
    const int h = bh % NH;
#pragma unroll
    for (int i = 0; i < 4; i++) {
        float inv = 1.f / l_i[i];
        float2 p0 = unpack2(o2[i][0]);
        float2 p1 = unpack2(o2[i][1]);
        int srow = qt * 64 + (ty << 2) + i;
        float* dst = g_ao + ((size_t)b * SEQ + srow) * DIM + h * HDIM + (tx << 2);
        *(float4*)dst = make_float4(p0.x * inv, p0.y * inv, p1.x * inv, p1.y * inv);
    }
}

// ---------------------------------------------------------------------------
// inputs: 0=q 1=k 2=v 3=attn_mask 4=Wq 5=bq 6=Wk 7=bk 8=Wv 9=bv 10=Wo 11=bo
// ---------------------------------------------------------------------------
extern "C" void kernel_launch(void* const* d_in, const int* in_sizes, int n_in,
                              void* d_out, int out_size)
{
    (void)in_sizes; (void)n_in; (void)out_size;
    const float* q  = (const float*)d_in[0];
    const float* k  = (const float*)d_in[1];
    const float* v  = (const float*)d_in[2];
    const float* Wq = (const float*)d_in[4];
    const float* bq = (const float*)d_in[5];
    const float* Wk = (const float*)d_in[6];
    const float* bk = (const float*)d_in[7];
    const float* Wv = (const float*)d_in[8];
    const float* bv = (const float*)d_in[9];
    const float* Wo = (const float*)d_in[10];
    const float* bo = (const float*)d_in[11];

    cudaFuncSetAttribute(attn_kernel, cudaFuncAttributeMaxDynamicSharedMemorySize,
                         ATTN_SMEM_BYTES);

    const int XG = MTOT * (DIM / 4);   // 1048576 groups
    const int WG = DIM * (DIM / 4);    //  262144 groups
    dim3 gg(DIM / GBN, MTOT / GBM);    // (8, 32)

    conv_aug<<<XG / 256, 256>>>(q, 0, 1, 0, XG);
    conv_aug<<<WG / 256, 256>>>(Wq, 1, 2, 0, WG);
    gemm_mma<<<gg, 256>>>(bq, nullptr, 0);

    conv_aug<<<XG / 256, 256>>>(k, 0, 1, 0, XG);
    conv_aug<<<WG / 256, 256>>>(Wk, 1, 2, 0, WG);
    gemm_mma<<<gg, 256>>>(bk, nullptr, 1);

    conv_aug<<<XG / 256, 256>>>(v, 0, 1, 0, XG);
    conv_aug<<<WG / 256, 256>>>(Wv, 1, 2, 0, WG);
    gemm_mma<<<gg, 256>>>(bv, nullptr, 2);

    attn_kernel<<<dim3(SEQ / 64, BB * NH), 256, ATTN_SMEM_BYTES>>>();

    conv_aug<<<XG / 256, 256>>>(nullptr, 0, 1, 1, XG);   // g_ao -> g_xaug
    conv_aug<<<WG / 256, 256>>>(Wo, 1, 2, 0, WG);
    gemm_mma<<<gg, 256>>>(bo, (float*)d_out, 3);
}

// round 9
// speedup vs baseline: 1.6892x; 1.2921x over previous
#include <cuda_runtime.h>
#include <cuda_bf16.h>
#include <cstdint>

// ---------------------------------------------------------------------------
// MultiHeadAttention: B=2, S=2048, D=1024, H=16, HD=64, causal.
// Round 9: attention ported to mma.sync m16n8k16 bf16 with fp32 hi/lo split
// on BOTH GEMMs (S=QK^T and O+=PV), 3-term augmentation [h,l,h]x[h,h,l].
// Projections keep the round-8 HMMA path (validated, 195 TF/s measured).
// ---------------------------------------------------------------------------

constexpr int BB   = 2;
constexpr int SEQ  = 2048;
constexpr int DIM  = 1024;
constexpr int NH   = 16;
constexpr int HDIM = 64;
constexpr int MTOT = BB * SEQ;          // 4096
constexpr float SCALE = 0.125f;

// ---- mma.sync projection GEMM ----
constexpr int KAUG = 3 * DIM;           // 3072
constexpr int GBM = 128, GBN = 128, GBK = 64;
constexpr int NKB  = KAUG / GBK;        // 48
constexpr int SPAD = 8;
constexpr int SROW = GBK + SPAD;        // 72 bf16

// ---- mma.sync attention ----
constexpr int QT = 128;                 // q rows per CTA
constexpr int KT = 64;                  // kv rows per tile
constexpr int AR = 136;                 // smem row: [hi 64 | lo 64] + 8 pad (bf16)
constexpr int SM_Q = 0;                 // 128 rows
constexpr int SM_K = SM_Q + QT * AR;    // 64 rows
constexpr int SM_V = SM_K + KT * AR;    // 64 rows (transposed: [hd][kv])
constexpr int SM_P = SM_V + KT * AR;    // 128 rows
constexpr int ATTN_SMEM2 = (SM_P + QT * AR) * 2;   // 104448 B

// Scratch (__device__ globals per allocation-free rule).
__device__ float g_qh[(size_t)BB * NH * SEQ * HDIM];
__device__ float g_kh[(size_t)BB * NH * SEQ * HDIM];
__device__ float g_vh[(size_t)BB * NH * SEQ * HDIM];
__device__ float g_ao[(size_t)BB * SEQ * DIM];
__device__ __align__(16) __nv_bfloat16 g_xaug[(size_t)MTOT * KAUG];
__device__ __align__(16) __nv_bfloat16 g_waug[(size_t)DIM  * KAUG];

// ---- mma.sync m16n8k16 bf16 (row.col), fp32 accumulate in-place ----
__device__ __forceinline__ void mma_bf16(float* d, const uint32_t* a,
                                         uint32_t b0, uint32_t b1) {
    asm volatile("mma.sync.aligned.m16n8k16.row.col.f32.bf16.bf16.f32 "
        "{%0,%1,%2,%3}, {%4,%5,%6,%7}, {%8,%9}, {%0,%1,%2,%3};"
        : "+f"(d[0]), "+f"(d[1]), "+f"(d[2]), "+f"(d[3])
        : "r"(a[0]), "r"(a[1]), "r"(a[2]), "r"(a[3]), "r"(b0), "r"(b1));
}

// split two floats into packed bf16 hi-pair and lo-pair
__device__ __forceinline__ void split2(float x, float y, uint32_t& hp, uint32_t& lp) {
    __nv_bfloat16 hx = __float2bfloat16(x), hy = __float2bfloat16(y);
    __nv_bfloat16 lx = __float2bfloat16(x - __bfloat162float(hx));
    __nv_bfloat16 ly = __float2bfloat16(y - __bfloat162float(hy));
    __nv_bfloat162 h; h.x = hx; h.y = hy; hp = *(uint32_t*)&h;
    __nv_bfloat162 l; l.x = lx; l.y = ly; lp = *(uint32_t*)&l;
}

// ============================================================================
// fp32 -> augmented bf16 hi/lo conversion for projections.
//   A (activations): lo_seg=1 -> [xh, xl, xh];  B (weights): lo_seg=2 -> [wh, wh, wl]
// ============================================================================
__global__ __launch_bounds__(256) void conv_aug(const float* __restrict__ Xin,
                                                int which_out, int lo_seg,
                                                int src_is_ao, int ngroups)
{
    int i = blockIdx.x * 256 + threadIdx.x;
    if (i >= ngroups) return;
    const float* X = src_is_ao ? g_ao : Xin;
    __nv_bfloat16* out = which_out ? g_waug : g_xaug;

    int m  = i >> 8;
    int kg = (i & 255) << 2;
    float4 v = *(const float4*)(X + (size_t)m * DIM + kg);

    uint32_t hA, lA, hB, lB;
    split2(v.x, v.y, hA, lA);
    split2(v.z, v.w, hB, lB);

    __nv_bfloat16* base = out + (size_t)m * KAUG + kg;
    *(uint32_t*)(base + 0) = hA;
    *(uint32_t*)(base + 2) = hB;
    *(uint32_t*)(base + DIM + 0)     = (lo_seg == 1) ? lA : hA;
    *(uint32_t*)(base + DIM + 2)     = (lo_seg == 1) ? lB : hB;
    *(uint32_t*)(base + 2 * DIM + 0) = (lo_seg == 2) ? lA : hA;
    *(uint32_t*)(base + 2 * DIM + 2) = (lo_seg == 2) ? lB : hB;
}

// ============================================================================
// HMMA projection GEMM (round-8, validated): Y = Xaug * Waug^T + bias
// ============================================================================
__global__ __launch_bounds__(256) void gemm_mma(const float* __restrict__ bias,
                                                float* __restrict__ Yout, int mode)
{
    __shared__ __align__(16) __nv_bfloat16 As[GBM][SROW];
    __shared__ __align__(16) __nv_bfloat16 Bs[GBN][SROW];

    const int tid = threadIdx.x;
    const int wid  = tid >> 5;
    const int lane = tid & 31;
    const int wm = wid >> 1;
    const int wn = wid & 1;
    const int r4 = lane >> 2;
    const int q2 = (lane & 3) << 1;
    const int n0 = blockIdx.x * GBN;
    const int m0 = blockIdx.y * GBM;

    const int lr = tid >> 1;
    const int ls = (tid & 1) << 2;

    float acc[2][8][4] = {};

    const __nv_bfloat16* ag = g_xaug + (size_t)(m0 + lr) * KAUG + ls * 8;
    const __nv_bfloat16* bg = g_waug + (size_t)(n0 + lr) * KAUG + ls * 8;

    for (int kb = 0; kb < NKB; kb++) {
        {
            const __nv_bfloat16* a = ag + kb * GBK;
            const __nv_bfloat16* b = bg + kb * GBK;
#pragma unroll
            for (int j = 0; j < 4; j++) {
                *(uint4*)&As[lr][(ls + j) * 8] = *(const uint4*)(a + j * 8);
                *(uint4*)&Bs[lr][(ls + j) * 8] = *(const uint4*)(b + j * 8);
            }
        }
        __syncthreads();

#pragma unroll
        for (int ka = 0; ka < 4; ka++) {
            const int k0 = ka * 16;
            uint32_t afr[2][4];
#pragma unroll
            for (int ma = 0; ma < 2; ma++) {
                const int R = wm * 32 + ma * 16;
                afr[ma][0] = *(const uint32_t*)&As[R + r4    ][k0 + q2    ];
                afr[ma][1] = *(const uint32_t*)&As[R + r4 + 8][k0 + q2    ];
                afr[ma][2] = *(const uint32_t*)&As[R + r4    ][k0 + q2 + 8];
                afr[ma][3] = *(const uint32_t*)&As[R + r4 + 8][k0 + q2 + 8];
            }
#pragma unroll
            for (int na = 0; na < 8; na++) {
                const int N = wn * 64 + na * 8;
                uint32_t b0 = *(const uint32_t*)&Bs[N + r4][k0 + q2    ];
                uint32_t b1 = *(const uint32_t*)&Bs[N + r4][k0 + q2 + 8];
                mma_bf16(acc[0][na], afr[0], b0, b1);
                mma_bf16(acc[1][na], afr[1], b0, b1);
            }
        }
        __syncthreads();
    }

    float* hdst = (mode == 0) ? g_qh : (mode == 1) ? g_kh : g_vh;
#pragma unroll
    for (int ma = 0; ma < 2; ma++) {
#pragma unroll
        for (int na = 0; na < 8; na++) {
            const int e  = n0 + wn * 64 + na * 8 + q2;
            const float2 bv = *(const float2*)(bias + e);
            const int row0 = m0 + wm * 32 + ma * 16 + r4;
#pragma unroll
            for (int h2i = 0; h2i < 2; h2i++) {
                const int m = row0 + h2i * 8;
                float2 rv = make_float2(acc[ma][na][h2i * 2 + 0] + bv.x,
                                        acc[ma][na][h2i * 2 + 1] + bv.y);
                if (mode == 3) {
                    *(float2*)(Yout + (size_t)m * DIM + e) = rv;
                } else {
                    const int b = m >> 11, s = m & (SEQ - 1);
                    const int h = e >> 6, hd = e & 63;
                    *(float2*)(hdst + (((size_t)(b * NH + h) * SEQ) + s) * HDIM + hd) = rv;
                }
            }
        }
    }
}

// ============================================================================
// HMMA flash attention: CTA = 128 q rows x one (b,h). 8 warps x (16 rows, 64 cols).
// S and PV both via m16n8k16 with hi/lo split, 12 k-steps [h,l,h]x[h,h,l].
// ============================================================================
__global__ __launch_bounds__(256) void attn_mma()
{
    extern __shared__ __align__(16) __nv_bfloat16 sb[];
    __nv_bfloat16* Qs = sb + SM_Q;   // [128][AR]  ([Qh|Ql], pre-scaled)
    __nv_bfloat16* Ks = sb + SM_K;   // [64][AR]   ([Kh|Kl], row=kv, col=hd)
    __nv_bfloat16* Vt = sb + SM_V;   // [64][AR]   ([Vh|Vl], row=hd, col=kv)
    __nv_bfloat16* Ps = sb + SM_P;   // [128][AR]  ([Ph|Pl])

    const int tid  = threadIdx.x;
    const int wid  = tid >> 5;
    const int lane = tid & 31;
    const int r4 = lane >> 2;
    const int q2 = (lane & 3) << 1;
    const int qt = blockIdx.x;
    const int bh = blockIdx.y;
    const int R  = wid * 16;
    const size_t base = (size_t)bh * SEQ;

    // ---- load + split Q tile (128 x 64), folding SCALE ----
    {
        const float* qp = g_qh + (base + (size_t)qt * QT) * HDIM;
#pragma unroll
        for (int t = 0; t < 8; t++) {
            int idx = tid + t * 256;          // 0..2047 float4s
            int row = idx >> 4, cg = (idx & 15) << 2;
            float4 v = *(const float4*)(qp + row * HDIM + cg);
            uint32_t hp, lp;
            split2(v.x * SCALE, v.y * SCALE, hp, lp);
            *(uint32_t*)&Qs[row * AR + cg]          = hp;
            *(uint32_t*)&Qs[row * AR + 64 + cg]     = lp;
            split2(v.z * SCALE, v.w * SCALE, hp, lp);
            *(uint32_t*)&Qs[row * AR + cg + 2]      = hp;
            *(uint32_t*)&Qs[row * AR + 64 + cg + 2] = lp;
        }
    }

    float m0 = -1e30f, m1 = -1e30f, l0 = 0.f, l1 = 0.f;
    float oacc[8][4] = {};
    const int nkt = 2 * qt + 2;

    for (int kt = 0; kt < nkt; kt++) {
        // ---- load + split K tile; V tile transposed ----
        {
            const float* kp = g_kh + (base + (size_t)kt * KT) * HDIM;
            const float* vp = g_vh + (base + (size_t)kt * KT) * HDIM;
#pragma unroll
            for (int t = 0; t < 4; t++) {
                int idx = tid + t * 256;      // 0..1023 float4s
                int row = idx >> 4, cg = (idx & 15) << 2;
                float4 kv4 = *(const float4*)(kp + row * HDIM + cg);
                uint32_t hp, lp;
                split2(kv4.x, kv4.y, hp, lp);
                *(uint32_t*)&Ks[row * AR + cg]          = hp;
                *(uint32_t*)&Ks[row * AR + 64 + cg]     = lp;
                split2(kv4.z, kv4.w, hp, lp);
                *(uint32_t*)&Ks[row * AR + cg + 2]      = hp;
                *(uint32_t*)&Ks[row * AR + 64 + cg + 2] = lp;

                float4 vv = *(const float4*)(vp + row * HDIM + cg);
                float va[4] = {vv.x, vv.y, vv.z, vv.w};
#pragma unroll
                for (int j = 0; j < 4; j++) {
                    __nv_bfloat16 h = __float2bfloat16(va[j]);
                    __nv_bfloat16 l = __float2bfloat16(va[j] - __bfloat162float(h));
                    Vt[(cg + j) * AR + row]      = h;
                    Vt[(cg + j) * AR + 64 + row] = l;
                }
            }
        }
        __syncthreads();

        // ---- S = Qaug Kaug^T  (12 k-steps, A:[h,l,h]  B:[h,h,l]) ----
        float sacc[8][4] = {};
#pragma unroll
        for (int s = 0; s < 12; s++) {
            const int s3 = s & 3;
            const int acol = (s >= 4 && s < 8) ? 64 + s3 * 16 : s3 * 16;
            const int bcol = (s < 8) ? s3 * 16 : 64 + s3 * 16;
            uint32_t af[4];
            af[0] = *(const uint32_t*)&Qs[(R + r4    ) * AR + acol + q2    ];
            af[1] = *(const uint32_t*)&Qs[(R + r4 + 8) * AR + acol + q2    ];
            af[2] = *(const uint32_t*)&Qs[(R + r4    ) * AR + acol + q2 + 8];
            af[3] = *(const uint32_t*)&Qs[(R + r4 + 8) * AR + acol + q2 + 8];
#pragma unroll
            for (int na = 0; na < 8; na++) {
                uint32_t b0 = *(const uint32_t*)&Ks[(na * 8 + r4) * AR + bcol + q2    ];
                uint32_t b1 = *(const uint32_t*)&Ks[(na * 8 + r4) * AR + bcol + q2 + 8];
                mma_bf16(sacc[na], af, b0, b1);
            }
        }

        // ---- causal mask (only the 2 diagonal tiles) ----
        if (kt >= nkt - 2) {
            const int row0 = qt * QT + R + r4, row1 = row0 + 8;
            const int c0 = kt * KT;
#pragma unroll
            for (int na = 0; na < 8; na++) {
                const int col = c0 + na * 8 + q2;
                if (col     > row0) sacc[na][0] = -1e30f;
                if (col + 1 > row0) sacc[na][1] = -1e30f;
                if (col     > row1) sacc[na][2] = -1e30f;
                if (col + 1 > row1) sacc[na][3] = -1e30f;
            }
        }

        // ---- online softmax (rows r4 and r4+8; quad shfl reduce) ----
        float tm0 = -1e30f, tm1 = -1e30f;
#pragma unroll
        for (int na = 0; na < 8; na++) {
            tm0 = fmaxf(tm0, fmaxf(sacc[na][0], sacc[na][1]));
            tm1 = fmaxf(tm1, fmaxf(sacc[na][2], sacc[na][3]));
        }
        tm0 = fmaxf(tm0, __shfl_xor_sync(0xffffffffu, tm0, 1));
        tm0 = fmaxf(tm0, __shfl_xor_sync(0xffffffffu, tm0, 2));
        tm1 = fmaxf(tm1, __shfl_xor_sync(0xffffffffu, tm1, 1));
        tm1 = fmaxf(tm1, __shfl_xor_sync(0xffffffffu, tm1, 2));
        const float mn0 = fmaxf(m0, tm0), mn1 = fmaxf(m1, tm1);
        const float fac0 = __expf(m0 - mn0), fac1 = __expf(m1 - mn1);
        m0 = mn0; m1 = mn1;
        float rs0 = 0.f, rs1 = 0.f;
#pragma unroll
        for (int na = 0; na < 8; na++) {
            sacc[na][0] = __expf(sacc[na][0] - mn0);
            sacc[na][1] = __expf(sacc[na][1] - mn0);
            sacc[na][2] = __expf(sacc[na][2] - mn1);
            sacc[na][3] = __expf(sacc[na][3] - mn1);
            rs0 += sacc[na][0] + sacc[na][1];
            rs1 += sacc[na][2] + sacc[na][3];
        }
        rs0 += __shfl_xor_sync(0xffffffffu, rs0, 1);
        rs0 += __shfl_xor_sync(0xffffffffu, rs0, 2);
        rs1 += __shfl_xor_sync(0xffffffffu, rs1, 1);
        rs1 += __shfl_xor_sync(0xffffffffu, rs1, 2);
        l0 = l0 * fac0 + rs0;
        l1 = l1 * fac1 + rs1;
#pragma unroll
        for (int na = 0; na < 8; na++) {
            oacc[na][0] *= fac0; oacc[na][1] *= fac0;
            oacc[na][2] *= fac1; oacc[na][3] *= fac1;
        }

        // ---- write P split to smem ----
#pragma unroll
        for (int na = 0; na < 8; na++) {
            const int col = na * 8 + q2;
            uint32_t hp, lp;
            split2(sacc[na][0], sacc[na][1], hp, lp);
            *(uint32_t*)&Ps[(R + r4) * AR + col]      = hp;
            *(uint32_t*)&Ps[(R + r4) * AR + 64 + col] = lp;
            split2(sacc[na][2], sacc[na][3], hp, lp);
            *(uint32_t*)&Ps[(R + r4 + 8) * AR + col]      = hp;
            *(uint32_t*)&Ps[(R + r4 + 8) * AR + 64 + col] = lp;
        }
        __syncthreads();

        // ---- O += Paug Vaug^T  (12 k-steps, A:[h,l,h]  B:[h,h,l]) ----
#pragma unroll
        for (int s = 0; s < 12; s++) {
            const int s3 = s & 3;
            const int acol = (s >= 4 && s < 8) ? 64 + s3 * 16 : s3 * 16;
            const int bcol = (s < 8) ? s3 * 16 : 64 + s3 * 16;
            uint32_t af[4];
            af[0] = *(const uint32_t*)&Ps[(R + r4    ) * AR + acol + q2    ];
            af[1] = *(const uint32_t*)&Ps[(R + r4 + 8) * AR + acol + q2    ];
            af[2] = *(const uint32_t*)&Ps[(R + r4    ) * AR + acol + q2 + 8];
            af[3] = *(const uint32_t*)&Ps[(R + r4 + 8) * AR + acol + q2 + 8];
#pragma unroll
            for (int na = 0; na < 8; na++) {
                uint32_t b0 = *(const uint32_t*)&Vt[(na * 8 + r4) * AR + bcol + q2    ];
                uint32_t b1 = *(const uint32_t*)&Vt[(na * 8 + r4) * AR + bcol + q2 + 8];
                mma_bf16(oacc[na], af, b0, b1);
            }
        }
        __syncthreads();
    }

    // ---- epilogue: O /= l, merged-head store to g_ao ----
    const int b = bh / NH, h = bh % NH;
    const float inv0 = 1.f / l0, inv1 = 1.f / l1;
    const int row0 = qt * QT + R + r4;
#pragma unroll
    for (int na = 0; na < 8; na++) {
        const int col = h * HDIM + na * 8 + q2;
        *(float2*)&g_ao[((size_t)b * SEQ + row0) * DIM + col] =
            make_float2(oacc[na][0] * inv0, oacc[na][1] * inv0);
        *(float2*)&g_ao[((size_t)b * SEQ + row0 + 8) * DIM + col] =
            make_float2(oacc[na][2] * inv1, oacc[na][3] * inv1);
    }
}

// ---------------------------------------------------------------------------
// inputs: 0=q 1=k 2=v 3=attn_mask 4=Wq 5=bq 6=Wk 7=bk 8=Wv 9=bv 10=Wo 11=bo
// ---------------------------------------------------------------------------
extern "C" void kernel_launch(void* const* d_in, const int* in_sizes, int n_in,
                              void* d_out, int out_size)
{
    (void)in_sizes; (void)n_in; (void)out_size;
    const float* q  = (const float*)d_in[0];
    const float* k  = (const float*)d_in[1];
    const float* v  = (const float*)d_in[2];
    const float* Wq = (const float*)d_in[4];
    const float* bq = (const float*)d_in[5];
    const float* Wk = (const float*)d_in[6];
    const float* bk = (const float*)d_in[7];
    const float* Wv = (const float*)d_in[8];
    const float* bv = (const float*)d_in[9];
    const float* Wo = (const float*)d_in[10];
    const float* bo = (const float*)d_in[11];

    cudaFuncSetAttribute(attn_mma, cudaFuncAttributeMaxDynamicSharedMemorySize,
                         ATTN_SMEM2);

    const int XG = MTOT * (DIM / 4);
    const int WG = DIM * (DIM / 4);
    dim3 gg(DIM / GBN, MTOT / GBM);    // (8, 32)

    conv_aug<<<XG / 256, 256>>>(q, 0, 1, 0, XG);
    conv_aug<<<WG / 256, 256>>>(Wq, 1, 2, 0, WG);
    gemm_mma<<<gg, 256>>>(bq, nullptr, 0);

    conv_aug<<<XG / 256, 256>>>(k, 0, 1, 0, XG);
    conv_aug<<<WG / 256, 256>>>(Wk, 1, 2, 0, WG);
    gemm_mma<<<gg, 256>>>(bk, nullptr, 1);

    conv_aug<<<XG / 256, 256>>>(v, 0, 1, 0, XG);
    conv_aug<<<WG / 256, 256>>>(Wv, 1, 2, 0, WG);
    gemm_mma<<<gg, 256>>>(bv, nullptr, 2);

    attn_mma<<<dim3(SEQ / QT, BB * NH), 256, ATTN_SMEM2>>>();

    conv_aug<<<XG / 256, 256>>>(nullptr, 0, 1, 1, XG);   // g_ao -> g_xaug
    conv_aug<<<WG / 256, 256>>>(Wo, 1, 2, 0, WG);
    gemm_mma<<<gg, 256>>>(bo, (float*)d_out, 3);
}

// round 12
// speedup vs baseline: 1.8149x; 1.0744x over previous
#include <cuda_runtime.h>
#include <cuda_bf16.h>
#include <cstdint>

// ---------------------------------------------------------------------------
// MultiHeadAttention: B=2, S=2048, D=1024, H=16, HD=64, causal.
// Round 12 (= round 10/11 retry, infra timeouts): projection GEMM with
// cp.async double-buffering + ldmatrix.x4 fragment loads + batched QKV launch
// (grid.z=3). Attention = round-9 HMMA flash kernel (validated).
// fp32 hi/lo bf16 split everywhere (3-term aug).
// ---------------------------------------------------------------------------

constexpr int BB   = 2;
constexpr int SEQ  = 2048;
constexpr int DIM  = 1024;
constexpr int NH   = 16;
constexpr int HDIM = 64;
constexpr int MTOT = BB * SEQ;          // 4096
constexpr float SCALE = 0.125f;

// ---- projection GEMM ----
constexpr int KAUG = 3 * DIM;           // 3072
constexpr int GBM = 128, GBN = 128, GBK = 64;
constexpr int NKB  = KAUG / GBK;        // 48
constexpr int SPAD = 8;
constexpr int SROW = GBK + SPAD;        // 72 bf16 = 144 B
constexpr int ABUF = GBM * SROW * 2;    // 18432 B per buffer
constexpr int GSMEM = 4 * ABUF;         // A[2] + B[2] = 73728 B
constexpr size_t XSZ = (size_t)MTOT * KAUG;
constexpr size_t WSZ = (size_t)DIM * KAUG;

// ---- attention ----
constexpr int QT = 128;
constexpr int KT = 64;
constexpr int AR = 136;
constexpr int SM_Q = 0;
constexpr int SM_K = SM_Q + QT * AR;
constexpr int SM_V = SM_K + KT * AR;
constexpr int SM_P = SM_V + KT * AR;
constexpr int ATTN_SMEM2 = (SM_P + QT * AR) * 2;   // 104448 B

// Scratch (__device__ globals per allocation-free rule).
__device__ float g_qh[(size_t)BB * NH * SEQ * HDIM];
__device__ float g_kh[(size_t)BB * NH * SEQ * HDIM];
__device__ float g_vh[(size_t)BB * NH * SEQ * HDIM];
__device__ float g_ao[(size_t)BB * SEQ * DIM];
__device__ __align__(16) __nv_bfloat16 g_xaug[3 * XSZ];   // 75.5 MB
__device__ __align__(16) __nv_bfloat16 g_waug[4 * WSZ];   // 25.2 MB

// ---- PTX helpers ----
__device__ __forceinline__ void mma_bf16(float* d, const uint32_t* a,
                                         uint32_t b0, uint32_t b1) {
    asm volatile("mma.sync.aligned.m16n8k16.row.col.f32.bf16.bf16.f32 "
        "{%0,%1,%2,%3}, {%4,%5,%6,%7}, {%8,%9}, {%0,%1,%2,%3};"
        : "+f"(d[0]), "+f"(d[1]), "+f"(d[2]), "+f"(d[3])
        : "r"(a[0]), "r"(a[1]), "r"(a[2]), "r"(a[3]), "r"(b0), "r"(b1));
}
__device__ __forceinline__ void ldm4(uint32_t* r, uint32_t addr) {
    asm volatile("ldmatrix.sync.aligned.m8n8.x4.shared.b16 {%0,%1,%2,%3}, [%4];"
        : "=r"(r[0]), "=r"(r[1]), "=r"(r[2]), "=r"(r[3]) : "r"(addr));
}
__device__ __forceinline__ void cp16(uint32_t smem, const void* g) {
    asm volatile("cp.async.cg.shared.global [%0], [%1], 16;" :: "r"(smem), "l"(g));
}
__device__ __forceinline__ void split2(float x, float y, uint32_t& hp, uint32_t& lp) {
    __nv_bfloat16 hx = __float2bfloat16(x), hy = __float2bfloat16(y);
    __nv_bfloat16 lx = __float2bfloat16(x - __bfloat162float(hx));
    __nv_bfloat16 ly = __float2bfloat16(y - __bfloat162float(hy));
    __nv_bfloat162 h; h.x = hx; h.y = hy; hp = *(uint32_t*)&h;
    __nv_bfloat162 l; l.x = lx; l.y = ly; lp = *(uint32_t*)&l;
}

// ============================================================================
// conv kernels: fp32 -> 3-term augmented bf16 hi/lo.
//   activations (lo_seg=1): [xh, xl, xh];  weights (lo_seg=2): [wh, wh, wl]
// ============================================================================
__device__ __forceinline__ void conv_row(const float* __restrict__ X,
                                         __nv_bfloat16* __restrict__ out,
                                         int i, int lo_seg)
{
    int m  = i >> 8;
    int kg = (i & 255) << 2;
    float4 v = *(const float4*)(X + (size_t)m * DIM + kg);
    uint32_t hA, lA, hB, lB;
    split2(v.x, v.y, hA, lA);
    split2(v.z, v.w, hB, lB);
    __nv_bfloat16* base = out + (size_t)m * KAUG + kg;
    *(uint32_t*)(base + 0) = hA;
    *(uint32_t*)(base + 2) = hB;
    *(uint32_t*)(base + DIM + 0)     = (lo_seg == 1) ? lA : hA;
    *(uint32_t*)(base + DIM + 2)     = (lo_seg == 1) ? lB : hB;
    *(uint32_t*)(base + 2 * DIM + 0) = (lo_seg == 2) ? lA : hA;
    *(uint32_t*)(base + 2 * DIM + 2) = (lo_seg == 2) ? lB : hB;
}

__global__ __launch_bounds__(256) void conv_x3(const float* __restrict__ x0,
                                               const float* __restrict__ x1,
                                               const float* __restrict__ x2)
{
    const int z = blockIdx.z;
    const float* X = (z == 0) ? x0 : (z == 1) ? x1 : x2;
    conv_row(X, g_xaug + (size_t)z * XSZ, blockIdx.x * 256 + threadIdx.x, 1);
}

__global__ __launch_bounds__(256) void conv_w4(const float* __restrict__ w0,
                                               const float* __restrict__ w1,
                                               const float* __restrict__ w2,
                                               const float* __restrict__ w3)
{
    const int z = blockIdx.z;
    const float* W = (z == 0) ? w0 : (z == 1) ? w1 : (z == 2) ? w2 : w3;
    conv_row(W, g_waug + (size_t)z * WSZ, blockIdx.x * 256 + threadIdx.x, 2);
}

__global__ __launch_bounds__(256) void conv_ao()
{
    conv_row(g_ao, g_xaug, blockIdx.x * 256 + threadIdx.x, 1);
}

// ============================================================================
// Pipelined HMMA projection GEMM: cp.async double-buffer + ldmatrix.x4.
// grid (8, 32, 3) for QKV (z selects buffers + scatter dst);
// grid (8, 32, 1) + final_mode=1 for the O projection (dense Yout).
// ============================================================================
__global__ __launch_bounds__(256, 2) void gemm_pipe(
    const float* __restrict__ b0p, const float* __restrict__ b1p,
    const float* __restrict__ b2p, float* __restrict__ Yout, int final_mode)
{
    extern __shared__ __align__(16) char smem[];
    const uint32_t sbase = (uint32_t)__cvta_generic_to_shared(smem);

    const int tid  = threadIdx.x;
    const int wid  = tid >> 5;
    const int lane = tid & 31;
    const int wm = wid >> 1;
    const int wn = wid & 1;
    const int r4 = lane >> 2;
    const int q2 = (lane & 3) << 1;
    const int z  = blockIdx.z;
    const int n0 = blockIdx.x * GBN;
    const int m0 = blockIdx.y * GBM;

    const int lr = tid >> 1;            // 0..127 gmem row
    const int ls = (tid & 1) << 2;      // 0 or 4: 16B-chunk base

    const __nv_bfloat16* ag = g_xaug + (final_mode ? 0 : (size_t)z * XSZ)
                            + (size_t)(m0 + lr) * KAUG + ls * 8;
    const __nv_bfloat16* bg = g_waug + (size_t)(final_mode ? 3 : z) * WSZ
                            + (size_t)(n0 + lr) * KAUG + ls * 8;
    const float* bias = (z == 0) ? b0p : (z == 1) ? b1p : b2p;

    // smem dst bases (bytes): A buffers at 0, B buffers at 2*ABUF
    const uint32_t da0 = sbase + (uint32_t)(lr * SROW + ls * 8) * 2;
    const uint32_t db0 = da0 + 2 * ABUF;

    float acc[2][8][4] = {};

    // prefetch tile 0 into buffer 0
    {
#pragma unroll
        for (int j = 0; j < 4; j++) {
            cp16(da0 + j * 16, ag + j * 8);
            cp16(db0 + j * 16, bg + j * 8);
        }
        asm volatile("cp.async.commit_group;" ::: "memory");
    }

    // fragment lane addressing (bytes, buffer-relative)
    const uint32_t a_lane = (uint32_t)(((lane & 15)) * SROW + (lane >> 4) * 8) * 2;
    const uint32_t b_lane = (uint32_t)(((lane >> 4) * 8 + (lane & 7)) * SROW
                                       + ((lane >> 3) & 1) * 8) * 2;

    for (int kb = 0; kb < NKB; kb++) {
        const int st = kb & 1;
        if (kb + 1 < NKB) {
            const __nv_bfloat16* a = ag + (size_t)(kb + 1) * GBK;
            const __nv_bfloat16* b = bg + (size_t)(kb + 1) * GBK;
            const uint32_t da = da0 + (st ^ 1) * ABUF;
            const uint32_t db = db0 + (st ^ 1) * ABUF;
#pragma unroll
            for (int j = 0; j < 4; j++) {
                cp16(da + j * 16, a + j * 8);
                cp16(db + j * 16, b + j * 8);
            }
            asm volatile("cp.async.commit_group;" ::: "memory");
            asm volatile("cp.async.wait_group 1;" ::: "memory");
        } else {
            asm volatile("cp.async.wait_group 0;" ::: "memory");
        }
        __syncthreads();

        const uint32_t Ab = sbase + st * ABUF;
        const uint32_t Bb = sbase + 2 * ABUF + st * ABUF;
#pragma unroll
        for (int ka = 0; ka < 4; ka++) {
            const int k0b = ka * 16 * 2;   // k offset in bytes
            uint32_t afr[2][4];
            ldm4(afr[0], Ab + a_lane + (uint32_t)(wm * 32) * SROW * 2 + k0b);
            ldm4(afr[1], Ab + a_lane + (uint32_t)(wm * 32 + 16) * SROW * 2 + k0b);
#pragma unroll
            for (int p = 0; p < 4; p++) {
                uint32_t bf[4];
                ldm4(bf, Bb + b_lane + (uint32_t)(wn * 64 + p * 16) * SROW * 2 + k0b);
                mma_bf16(acc[0][2 * p    ], afr[0], bf[0], bf[1]);
                mma_bf16(acc[1][2 * p    ], afr[1], bf[0], bf[1]);
                mma_bf16(acc[0][2 * p + 1], afr[0], bf[2], bf[3]);
                mma_bf16(acc[1][2 * p + 1], afr[1], bf[2], bf[3]);
            }
        }
        __syncthreads();
    }

    // epilogue
    float* hdst = (z == 0) ? g_qh : (z == 1) ? g_kh : g_vh;
#pragma unroll
    for (int ma = 0; ma < 2; ma++) {
#pragma unroll
        for (int na = 0; na < 8; na++) {
            const int e  = n0 + wn * 64 + na * 8 + q2;
            const float2 bv = *(const float2*)(bias + e);
            const int row0 = m0 + wm * 32 + ma * 16 + r4;
#pragma unroll
            for (int h2i = 0; h2i < 2; h2i++) {
                const int m = row0 + h2i * 8;
                float2 rv = make_float2(acc[ma][na][h2i * 2 + 0] + bv.x,
                                        acc[ma][na][h2i * 2 + 1] + bv.y);
                if (final_mode) {
                    *(float2*)(Yout + (size_t)m * DIM + e) = rv;
                } else {
                    const int b = m >> 11, s = m & (SEQ - 1);
                    const int h = e >> 6, hd = e & 63;
                    *(float2*)(hdst + (((size_t)(b * NH + h) * SEQ) + s) * HDIM + hd) = rv;
                }
            }
        }
    }
}

// ============================================================================
// HMMA flash attention (round-9, validated).
// ============================================================================
__global__ __launch_bounds__(256) void attn_mma()
{
    extern __shared__ __align__(16) __nv_bfloat16 sb[];
    __nv_bfloat16* Qs = sb + SM_Q;
    __nv_bfloat16* Ks = sb + SM_K;
    __nv_bfloat16* Vt = sb + SM_V;
    __nv_bfloat16* Ps = sb + SM_P;

    const int tid  = threadIdx.x;
    const int wid  = tid >> 5;
    const int lane = tid & 31;
    const int r4 = lane >> 2;
    const int q2 = (lane & 3) << 1;
    const int qt = blockIdx.x;
    const int bh = blockIdx.y;
    const int R  = wid * 16;
    const size_t base = (size_t)bh * SEQ;

    {
        const float* qp = g_qh + (base + (size_t)qt * QT) * HDIM;
#pragma unroll
        for (int t = 0; t < 8; t++) {
            int idx = tid + t * 256;
            int row = idx >> 4, cg = (idx & 15) << 2;
            float4 v = *(const float4*)(qp + row * HDIM + cg);
            uint32_t hp, lp;
            split2(v.x * SCALE, v.y * SCALE, hp, lp);
            *(uint32_t*)&Qs[row * AR + cg]          = hp;
            *(uint32_t*)&Qs[row * AR + 64 + cg]     = lp;
            split2(v.z * SCALE, v.w * SCALE, hp, lp);
            *(uint32_t*)&Qs[row * AR + cg + 2]      = hp;
            *(uint32_t*)&Qs[row * AR + 64 + cg + 2] = lp;
        }
    }

    float m0 = -1e30f, m1 = -1e30f, l0 = 0.f, l1 = 0.f;
    float oacc[8][4] = {};
    const int nkt = 2 * qt + 2;

    for (int kt = 0; kt < nkt; kt++) {
        {
            const float* kp = g_kh + (base + (size_t)kt * KT) * HDIM;
            const float* vp = g_vh + (base + (size_t)kt * KT) * HDIM;
#pragma unroll
            for (int t = 0; t < 4; t++) {
                int idx = tid + t * 256;
                int row = idx >> 4, cg = (idx & 15) << 2;
                float4 kv4 = *(const float4*)(kp + row * HDIM + cg);
                uint32_t hp, lp;
                split2(kv4.x, kv4.y, hp, lp);
                *(uint32_t*)&Ks[row * AR + cg]          = hp;
                *(uint32_t*)&Ks[row * AR + 64 + cg]     = lp;
                split2(kv4.z, kv4.w, hp, lp);
                *(uint32_t*)&Ks[row * AR + cg + 2]      = hp;
                *(uint32_t*)&Ks[row * AR + 64 + cg + 2] = lp;

                float4 vv = *(const float4*)(vp + row * HDIM + cg);
                float va[4] = {vv.x, vv.y, vv.z, vv.w};
#pragma unroll
                for (int j = 0; j < 4; j++) {
                    __nv_bfloat16 h = __float2bfloat16(va[j]);
                    __nv_bfloat16 l = __float2bfloat16(va[j] - __bfloat162float(h));
                    Vt[(cg + j) * AR + row]      = h;
                    Vt[(cg + j) * AR + 64 + row] = l;
                }
            }
        }
        __syncthreads();

        float sacc[8][4] = {};
#pragma unroll
        for (int s = 0; s < 12; s++) {
            const int s3 = s & 3;
            const int acol = (s >= 4 && s < 8) ? 64 + s3 * 16 : s3 * 16;
            const int bcol = (s < 8) ? s3 * 16 : 64 + s3 * 16;
            uint32_t af[4];
            af[0] = *(const uint32_t*)&Qs[(R + r4    ) * AR + acol + q2    ];
            af[1] = *(const uint32_t*)&Qs[(R + r4 + 8) * AR + acol + q2    ];
            af[2] = *(const uint32_t*)&Qs[(R + r4    ) * AR + acol + q2 + 8];
            af[3] = *(const uint32_t*)&Qs[(R + r4 + 8) * AR + acol + q2 + 8];
#pragma unroll
            for (int na = 0; na < 8; na++) {
                uint32_t b0 = *(const uint32_t*)&Ks[(na * 8 + r4) * AR + bcol + q2    ];
                uint32_t b1 = *(const uint32_t*)&Ks[(na * 8 + r4) * AR + bcol + q2 + 8];
                mma_bf16(sacc[na], af, b0, b1);
            }
        }

        if (kt >= nkt - 2) {
            const int row0 = qt * QT + R + r4, row1 = row0 + 8;
            const int c0 = kt * KT;
#pragma unroll
            for (int na = 0; na < 8; na++) {
                const int col = c0 + na * 8 + q2;
                if (col     > row0) sacc[na][0] = -1e30f;
                if (col + 1 > row0) sacc[na][1] = -1e30f;
                if (col     > row1) sacc[na][2] = -1e30f;
                if (col + 1 > row1) sacc[na][3] = -1e30f;
            }
        }

        float tm0 = -1e30f, tm1 = -1e30f;
#pragma unroll
        for (int na = 0; na < 8; na++) {
            tm0 = fmaxf(tm0, fmaxf(sacc[na][0], sacc[na][1]));
            tm1 = fmaxf(tm1, fmaxf(sacc[na][2], sacc[na][3]));
        }
        tm0 = fmaxf(tm0, __shfl_xor_sync(0xffffffffu, tm0, 1));
        tm0 = fmaxf(tm0, __shfl_xor_sync(0xffffffffu, tm0, 2));
        tm1 = fmaxf(tm1, __shfl_xor_sync(0xffffffffu, tm1, 1));
        tm1 = fmaxf(tm1, __shfl_xor_sync(0xffffffffu, tm1, 2));
        const float mn0 = fmaxf(m0, tm0), mn1 = fmaxf(m1, tm1);
        const float fac0 = __expf(m0 - mn0), fac1 = __expf(m1 - mn1);
        m0 = mn0; m1 = mn1;
        float rs0 = 0.f, rs1 = 0.f;
#pragma unroll
        for (int na = 0; na < 8; na++) {
            sacc[na][0] = __expf(sacc[na][0] - mn0);
            sacc[na][1] = __expf(sacc[na][1] - mn0);
            sacc[na][2] = __expf(sacc[na][2] - mn1);
            sacc[na][3] = __expf(sacc[na][3] - mn1);
            rs0 += sacc[na][0] + sacc[na][1];
            rs1 += sacc[na][2] + sacc[na][3];
        }
        rs0 += __shfl_xor_sync(0xffffffffu, rs0, 1);
        rs0 += __shfl_xor_sync(0xffffffffu, rs0, 2);
        rs1 += __shfl_xor_sync(0xffffffffu, rs1, 1);
        rs1 += __shfl_xor_sync(0xffffffffu, rs1, 2);
        l0 = l0 * fac0 + rs0;
        l1 = l1 * fac1 + rs1;
#pragma unroll
        for (int na = 0; na < 8; na++) {
            oacc[na][0] *= fac0; oacc[na][1] *= fac0;
            oacc[na][2] *= fac1; oacc[na][3] *= fac1;
        }

#pragma unroll
        for (int na = 0; na < 8; na++) {
            const int col = na * 8 + q2;
            uint32_t hp, lp;
            split2(sacc[na][0], sacc[na][1], hp, lp);
            *(uint32_t*)&Ps[(R + r4) * AR + col]      = hp;
            *(uint32_t*)&Ps[(R + r4) * AR + 64 + col] = lp;
            split2(sacc[na][2], sacc[na][3], hp, lp);
            *(uint32_t*)&Ps[(R + r4 + 8) * AR + col]      = hp;
            *(uint32_t*)&Ps[(R + r4 + 8) * AR + 64 + col] = lp;
        }
        __syncthreads();

#pragma unroll
        for (int s = 0; s < 12; s++) {
            const int s3 = s & 3;
            const int acol = (s >= 4 && s < 8) ? 64 + s3 * 16 : s3 * 16;
            const int bcol = (s < 8) ? s3 * 16 : 64 + s3 * 16;
            uint32_t af[4];
            af[0] = *(const uint32_t*)&Ps[(R + r4    ) * AR + acol + q2    ];
            af[1] = *(const uint32_t*)&Ps[(R + r4 + 8) * AR + acol + q2    ];
            af[2] = *(const uint32_t*)&Ps[(R + r4    ) * AR + acol + q2 + 8];
            af[3] = *(const uint32_t*)&Ps[(R + r4 + 8) * AR + acol + q2 + 8];
#pragma unroll
            for (int na = 0; na < 8; na++) {
                uint32_t b0 = *(const uint32_t*)&Vt[(na * 8 + r4) * AR + bcol + q2    ];
                uint32_t b1 = *(const uint32_t*)&Vt[(na * 8 + r4) * AR + bcol + q2 + 8];
                mma_bf16(oacc[na], af, b0, b1);
            }
        }
        __syncthreads();
    }

    const int b = bh / NH, h = bh % NH;
    const float inv0 = 1.f / l0, inv1 = 1.f / l1;
    const int row0 = qt * QT + R + r4;
#pragma unroll
    for (int na = 0; na < 8; na++) {
        const int col = h * HDIM + na * 8 + q2;
        *(float2*)&g_ao[((size_t)b * SEQ + row0) * DIM + col] =
            make_float2(oacc[na][0] * inv0, oacc[na][1] * inv0);
        *(float2*)&g_ao[((size_t)b * SEQ + row0 + 8) * DIM + col] =
            make_float2(oacc[na][2] * inv1, oacc[na][3] * inv1);
    }
}

// ---------------------------------------------------------------------------
// inputs: 0=q 1=k 2=v 3=attn_mask 4=Wq 5=bq 6=Wk 7=bk 8=Wv 9=bv 10=Wo 11=bo
// ---------------------------------------------------------------------------
extern "C" void kernel_launch(void* const* d_in, const int* in_sizes, int n_in,
                              void* d_out, int out_size)
{
    (void)in_sizes; (void)n_in; (void)out_size;
    const float* q  = (const float*)d_in[0];
    const float* k  = (const float*)d_in[1];
    const float* v  = (const float*)d_in[2];
    const float* Wq = (const float*)d_in[4];
    const float* bq = (const float*)d_in[5];
    const float* Wk = (const float*)d_in[6];
    const float* bk = (const float*)d_in[7];
    const float* Wv = (const float*)d_in[8];
    const float* bv = (const float*)d_in[9];
    const float* Wo = (const float*)d_in[10];
    const float* bo = (const float*)d_in[11];

    cudaFuncSetAttribute(gemm_pipe, cudaFuncAttributeMaxDynamicSharedMemorySize, GSMEM);
    cudaFuncSetAttribute(attn_mma, cudaFuncAttributeMaxDynamicSharedMemorySize,
                         ATTN_SMEM2);

    const int XG = MTOT * (DIM / 4);   // 1048576
    const int WG = DIM * (DIM / 4);    //  262144

    conv_x3<<<dim3(XG / 256, 1, 3), 256>>>(q, k, v);
    conv_w4<<<dim3(WG / 256, 1, 4), 256>>>(Wq, Wk, Wv, Wo);
    gemm_pipe<<<dim3(DIM / GBN, MTOT / GBM, 3), 256, GSMEM>>>(bq, bk, bv, nullptr, 0);

    attn_mma<<<dim3(SEQ / QT, BB * NH), 256, ATTN_SMEM2>>>();

    conv_ao<<<XG / 256, 256>>>();
    gemm_pipe<<<dim3(DIM / GBN, MTOT / GBM, 1), 256, GSMEM>>>(bo, bo, bo,
                                                              (float*)d_out, 1);
}

// round 16
// speedup vs baseline: 2.0408x; 1.1245x over previous
#include <cuda_runtime.h>
#include <cuda_bf16.h>
#include <cstdint>

// ---------------------------------------------------------------------------
// MultiHeadAttention: B=2, S=2048, D=1024, H=16, HD=64, causal.
// Round 16 (= round 13/14/15 retry, infra timeouts): attention restructured —
// pre-split Q/K (conv_qk) and transposed pre-split V (conv_vt) in gmem; attn
// uses cp.async double-buffered K/V tiles + ldmatrix.x4 for Q/K/P/V fragments.
// qt launch order reversed for balance. Projections: round-12 pipelined HMMA.
// 3-term hi/lo bf16 aug everywhere.
// ---------------------------------------------------------------------------

constexpr int BB   = 2;
constexpr int SEQ  = 2048;
constexpr int DIM  = 1024;
constexpr int NH   = 16;
constexpr int HDIM = 64;
constexpr int MTOT = BB * SEQ;          // 4096
constexpr int BH   = BB * NH;           // 32
constexpr float SCALE = 0.125f;

// ---- projection GEMM ----
constexpr int KAUG = 3 * DIM;           // 3072
constexpr int GBM = 128, GBN = 128, GBK = 64;
constexpr int NKB  = KAUG / GBK;        // 48
constexpr int SPAD = 8;
constexpr int SROW = GBK + SPAD;        // 72 bf16 = 144 B
constexpr int ABUF = GBM * SROW * 2;    // 18432 B
constexpr int GSMEM = 4 * ABUF;         // 73728 B
constexpr size_t XSZ = (size_t)MTOT * KAUG;
constexpr size_t WSZ = (size_t)DIM * KAUG;

// ---- attention ----
constexpr int QT = 128;
constexpr int KT = 64;
constexpr int AR = 136;                 // smem row stride (bf16): [hi64|lo64]+pad
constexpr int ATTN_SMEM3 = 512 * AR * 2;   // Q(128)+K(2x64)+V(2x64)+P(128) = 139264 B

// Scratch (__device__ globals per allocation-free rule).
__device__ float g_qh[(size_t)BH * SEQ * HDIM];
__device__ float g_kh[(size_t)BH * SEQ * HDIM];
__device__ float g_vh[(size_t)BH * SEQ * HDIM];
__device__ float g_ao[(size_t)BB * SEQ * DIM];
__device__ __align__(16) __nv_bfloat16 g_xaug[3 * XSZ];
__device__ __align__(16) __nv_bfloat16 g_waug[4 * WSZ];
__device__ __align__(16) __nv_bfloat16 g_qs[(size_t)BH * SEQ * 128];     // [s][hi64|lo64]
__device__ __align__(16) __nv_bfloat16 g_ks[(size_t)BH * SEQ * 128];
__device__ __align__(16) __nv_bfloat16 g_vt[(size_t)BH * HDIM * 2 * SEQ]; // [hd][S-hi|S-lo]

// ---- PTX helpers ----
__device__ __forceinline__ void mma_bf16(float* d, const uint32_t* a,
                                         uint32_t b0, uint32_t b1) {
    asm volatile("mma.sync.aligned.m16n8k16.row.col.f32.bf16.bf16.f32 "
        "{%0,%1,%2,%3}, {%4,%5,%6,%7}, {%8,%9}, {%0,%1,%2,%3};"
        : "+f"(d[0]), "+f"(d[1]), "+f"(d[2]), "+f"(d[3])
        : "r"(a[0]), "r"(a[1]), "r"(a[2]), "r"(a[3]), "r"(b0), "r"(b1));
}
__device__ __forceinline__ void ldm4(uint32_t* r, uint32_t addr) {
    asm volatile("ldmatrix.sync.aligned.m8n8.x4.shared.b16 {%0,%1,%2,%3}, [%4];"
        : "=r"(r[0]), "=r"(r[1]), "=r"(r[2]), "=r"(r[3]) : "r"(addr));
}
__device__ __forceinline__ void cp16(uint32_t smem, const void* g) {
    asm volatile("cp.async.cg.shared.global [%0], [%1], 16;" :: "r"(smem), "l"(g));
}
__device__ __forceinline__ void cp_commit() {
    asm volatile("cp.async.commit_group;" ::: "memory");
}
__device__ __forceinline__ void split2(float x, float y, uint32_t& hp, uint32_t& lp) {
    __nv_bfloat16 hx = __float2bfloat16(x), hy = __float2bfloat16(y);
    __nv_bfloat16 lx = __float2bfloat16(x - __bfloat162float(hx));
    __nv_bfloat16 ly = __float2bfloat16(y - __bfloat162float(hy));
    __nv_bfloat162 h; h.x = hx; h.y = hy; hp = *(uint32_t*)&h;
    __nv_bfloat162 l; l.x = lx; l.y = ly; lp = *(uint32_t*)&l;
}

// ============================================================================
// conv kernels for projections (round-8, validated)
// ============================================================================
__device__ __forceinline__ void conv_row(const float* __restrict__ X,
                                         __nv_bfloat16* __restrict__ out,
                                         int i, int lo_seg)
{
    int m  = i >> 8;
    int kg = (i & 255) << 2;
    float4 v = *(const float4*)(X + (size_t)m * DIM + kg);
    uint32_t hA, lA, hB, lB;
    split2(v.x, v.y, hA, lA);
    split2(v.z, v.w, hB, lB);
    __nv_bfloat16* base = out + (size_t)m * KAUG + kg;
    *(uint32_t*)(base + 0) = hA;
    *(uint32_t*)(base + 2) = hB;
    *(uint32_t*)(base + DIM + 0)     = (lo_seg == 1) ? lA : hA;
    *(uint32_t*)(base + DIM + 2)     = (lo_seg == 1) ? lB : hB;
    *(uint32_t*)(base + 2 * DIM + 0) = (lo_seg == 2) ? lA : hA;
    *(uint32_t*)(base + 2 * DIM + 2) = (lo_seg == 2) ? lB : hB;
}

__global__ __launch_bounds__(256) void conv_x3(const float* __restrict__ x0,
                                               const float* __restrict__ x1,
                                               const float* __restrict__ x2)
{
    const int z = blockIdx.z;
    const float* X = (z == 0) ? x0 : (z == 1) ? x1 : x2;
    conv_row(X, g_xaug + (size_t)z * XSZ, blockIdx.x * 256 + threadIdx.x, 1);
}

__global__ __launch_bounds__(256) void conv_w4(const float* __restrict__ w0,
                                               const float* __restrict__ w1,
                                               const float* __restrict__ w2,
                                               const float* __restrict__ w3)
{
    const int z = blockIdx.z;
    const float* W = (z == 0) ? w0 : (z == 1) ? w1 : (z == 2) ? w2 : w3;
    conv_row(W, g_waug + (size_t)z * WSZ, blockIdx.x * 256 + threadIdx.x, 2);
}

__global__ __launch_bounds__(256) void conv_ao()
{
    conv_row(g_ao, g_xaug, blockIdx.x * 256 + threadIdx.x, 1);
}

// ============================================================================
// attention pre-split kernels
// conv_qk: z=0 Q*SCALE -> g_qs; z=1 K -> g_ks.  Row layout [hi64|lo64].
// ============================================================================
__global__ __launch_bounds__(256) void conv_qk()
{
    const int z = blockIdx.z;
    const float* src = z ? g_kh : g_qh;
    __nv_bfloat16* dst = z ? g_ks : g_qs;
    const float sc = z ? 1.0f : SCALE;

    int i = blockIdx.x * 256 + threadIdx.x;      // 0..BH*SEQ*16-1
    int row = i >> 4, cg = (i & 15) << 2;
    float4 v = *(const float4*)(src + (size_t)row * HDIM + cg);
    uint32_t h0, l0, h1, l1;
    split2(v.x * sc, v.y * sc, h0, l0);
    split2(v.z * sc, v.w * sc, h1, l1);
    __nv_bfloat16* o = dst + (size_t)row * 128 + cg;
    *(uint32_t*)(o + 0)      = h0;
    *(uint32_t*)(o + 2)      = h1;
    *(uint32_t*)(o + 64)     = l0;
    *(uint32_t*)(o + 64 + 2) = l1;
}

// conv_vt: V [bh][s][hd] -> g_vt [bh][hd][S-hi | S-lo], smem-staged transpose.
__global__ __launch_bounds__(256) void conv_vt()
{
    __shared__ float tile[64][65];
    const int tid = threadIdx.x;
    const int kt = blockIdx.x, bh = blockIdx.y;
    const int wid = tid >> 5, lane = tid & 31;

    const float* src = g_vh + ((size_t)bh * SEQ + kt * 64) * HDIM;
#pragma unroll
    for (int j = 0; j < 4; j++) {
        int idx = tid + j * 256;
        int row = idx >> 4, cg = (idx & 15) << 2;
        float4 v = *(const float4*)(src + row * HDIM + cg);
        tile[row][cg + 0] = v.x; tile[row][cg + 1] = v.y;
        tile[row][cg + 2] = v.z; tile[row][cg + 3] = v.w;
    }
    __syncthreads();

#pragma unroll
    for (int r = 0; r < 8; r++) {
        const int hd = wid * 8 + r;
        const int s2 = lane * 2;
        uint32_t hp, lp;
        split2(tile[s2][hd], tile[s2 + 1][hd], hp, lp);
        __nv_bfloat16* dst = g_vt + ((size_t)bh * HDIM + hd) * 2 * SEQ;
        *(uint32_t*)(dst + kt * 64 + s2)       = hp;
        *(uint32_t*)(dst + SEQ + kt * 64 + s2) = lp;
    }
}

// ============================================================================
// Pipelined HMMA projection GEMM (round-12, validated)
// ============================================================================
__global__ __launch_bounds__(256, 2) void gemm_pipe(
    const float* __restrict__ b0p, const float* __restrict__ b1p,
    const float* __restrict__ b2p, float* __restrict__ Yout, int final_mode)
{
    extern __shared__ __align__(16) char smem[];
    const uint32_t sbase = (uint32_t)__cvta_generic_to_shared(smem);

    const int tid  = threadIdx.x;
    const int lane = tid & 31;
    const int wid  = tid >> 5;
    const int wm = wid >> 1;
    const int wn = wid & 1;
    const int r4 = lane >> 2;
    const int q2 = (lane & 3) << 1;
    const int z  = blockIdx.z;
    const int n0 = blockIdx.x * GBN;
    const int m0 = blockIdx.y * GBM;

    const int lr = tid >> 1;
    const int ls = (tid & 1) << 2;

    const __nv_bfloat16* ag = g_xaug + (final_mode ? 0 : (size_t)z * XSZ)
                            + (size_t)(m0 + lr) * KAUG + ls * 8;
    const __nv_bfloat16* bg = g_waug + (size_t)(final_mode ? 3 : z) * WSZ
                            + (size_t)(n0 + lr) * KAUG + ls * 8;
    const float* bias = (z == 0) ? b0p : (z == 1) ? b1p : b2p;

    const uint32_t da0 = sbase + (uint32_t)(lr * SROW + ls * 8) * 2;
    const uint32_t db0 = da0 + 2 * ABUF;

    float acc[2][8][4] = {};

    {
#pragma unroll
        for (int j = 0; j < 4; j++) {
            cp16(da0 + j * 16, ag + j * 8);
            cp16(db0 + j * 16, bg + j * 8);
        }
        cp_commit();
    }

    const uint32_t a_lane = (uint32_t)(((lane & 15)) * SROW + (lane >> 4) * 8) * 2;
    const uint32_t b_lane = (uint32_t)(((lane >> 4) * 8 + (lane & 7)) * SROW
                                       + ((lane >> 3) & 1) * 8) * 2;

    for (int kb = 0; kb < NKB; kb++) {
        const int st = kb & 1;
        if (kb + 1 < NKB) {
            const __nv_bfloat16* a = ag + (size_t)(kb + 1) * GBK;
            const __nv_bfloat16* b = bg + (size_t)(kb + 1) * GBK;
            const uint32_t da = da0 + (st ^ 1) * ABUF;
            const uint32_t db = db0 + (st ^ 1) * ABUF;
#pragma unroll
            for (int j = 0; j < 4; j++) {
                cp16(da + j * 16, a + j * 8);
                cp16(db + j * 16, b + j * 8);
            }
            cp_commit();
            asm volatile("cp.async.wait_group 1;" ::: "memory");
        } else {
            asm volatile("cp.async.wait_group 0;" ::: "memory");
        }
        __syncthreads();

        const uint32_t Ab = sbase + st * ABUF;
        const uint32_t Bb = sbase + 2 * ABUF + st * ABUF;
#pragma unroll
        for (int ka = 0; ka < 4; ka++) {
            const int k0b = ka * 16 * 2;
            uint32_t afr[2][4];
            ldm4(afr[0], Ab + a_lane + (uint32_t)(wm * 32) * SROW * 2 + k0b);
            ldm4(afr[1], Ab + a_lane + (uint32_t)(wm * 32 + 16) * SROW * 2 + k0b);
#pragma unroll
            for (int p = 0; p < 4; p++) {
                uint32_t bf[4];
                ldm4(bf, Bb + b_lane + (uint32_t)(wn * 64 + p * 16) * SROW * 2 + k0b);
                mma_bf16(acc[0][2 * p    ], afr[0], bf[0], bf[1]);
                mma_bf16(acc[1][2 * p    ], afr[1], bf[0], bf[1]);
                mma_bf16(acc[0][2 * p + 1], afr[0], bf[2], bf[3]);
                mma_bf16(acc[1][2 * p + 1], afr[1], bf[2], bf[3]);
            }
        }
        __syncthreads();
    }

    float* hdst = (z == 0) ? g_qh : (z == 1) ? g_kh : g_vh;
#pragma unroll
    for (int ma = 0; ma < 2; ma++) {
#pragma unroll
        for (int na = 0; na < 8; na++) {
            const int e  = n0 + wn * 64 + na * 8 + q2;
            const float2 bv = *(const float2*)(bias + e);
            const int row0 = m0 + wm * 32 + ma * 16 + r4;
#pragma unroll
            for (int h2i = 0; h2i < 2; h2i++) {
                const int m = row0 + h2i * 8;
                float2 rv = make_float2(acc[ma][na][h2i * 2 + 0] + bv.x,
                                        acc[ma][na][h2i * 2 + 1] + bv.y);
                if (final_mode) {
                    *(float2*)(Yout + (size_t)m * DIM + e) = rv;
                } else {
                    const int b = m >> 11, s = m & (SEQ - 1);
                    const int h = e >> 6, hd = e & 63;
                    *(float2*)(hdst + (((size_t)(b * NH + h) * SEQ) + s) * HDIM + hd) = rv;
                }
            }
        }
    }
}

// ============================================================================
// HMMA flash attention v2: pre-split gmem operands, cp.async double-buffered
// K/V, ldmatrix.x4 fragments. col mapping na*8+q2 (== validated gemm mapping).
// ============================================================================
__global__ __launch_bounds__(256) void attn_mma2()
{
    extern __shared__ __align__(16) __nv_bfloat16 sb[];
    const uint32_t sbase = (uint32_t)__cvta_generic_to_shared(sb);
    const uint32_t Qb  = sbase;                       // 128*AR
    const uint32_t Kb0 = sbase + 128 * AR * 2;        // 2 x 64*AR
    const uint32_t Vb0 = sbase + 256 * AR * 2;        // 2 x 64*AR
    const uint32_t Pb  = sbase + 384 * AR * 2;        // 128*AR
    const uint32_t KVs = 64 * AR * 2;
    __nv_bfloat16* Ps = sb + 384 * AR;

    const int tid  = threadIdx.x;
    const int wid  = tid >> 5;
    const int lane = tid & 31;
    const int r4 = lane >> 2;
    const int q2 = (lane & 3) << 1;
    const int qt = gridDim.x - 1 - blockIdx.x;        // long diagonals first
    const int bh = blockIdx.y;
    const int R  = wid * 16;
    const int nkt = 2 * qt + 2;

    const __nv_bfloat16* ksrc = g_ks + (size_t)bh * SEQ * 128;
    const __nv_bfloat16* vsrc = g_vt + (size_t)bh * HDIM * 2 * SEQ;

    // Q prefetch (whole 128x[hi|lo] tile)
    {
        const __nv_bfloat16* qsrc = g_qs + ((size_t)bh * SEQ + qt * QT) * 128;
#pragma unroll
        for (int j = 0; j < 8; j++) {
            int c = tid + j * 256;
            int row = c >> 4, seg = c & 15;
            cp16(Qb + (uint32_t)(row * AR + seg * 8) * 2, qsrc + row * 128 + seg * 8);
        }
    }
    // K/V tile 0
    {
#pragma unroll
        for (int j = 0; j < 4; j++) {
            int c = tid + j * 256;
            int row = c >> 4, seg = c & 15;
            cp16(Kb0 + (uint32_t)(row * AR + seg * 8) * 2,
                 ksrc + (size_t)row * 128 + seg * 8);
            const __nv_bfloat16* vs = (seg < 8)
                ? vsrc + (size_t)row * 2 * SEQ + seg * 8
                : vsrc + (size_t)row * 2 * SEQ + SEQ + (seg - 8) * 8;
            cp16(Vb0 + (uint32_t)(row * AR + seg * 8) * 2, vs);
        }
    }
    cp_commit();

    const uint32_t a_lane = (uint32_t)((lane & 15) * AR + (lane >> 4) * 8) * 2;
    const uint32_t b_lane = (uint32_t)(((lane >> 4) * 8 + (lane & 7)) * AR
                                       + ((lane >> 3) & 1) * 8) * 2;

    float m0 = -1e30f, m1 = -1e30f, l0 = 0.f, l1 = 0.f;
    float oacc[8][4] = {};

    for (int kt = 0; kt < nkt; kt++) {
        const int st = kt & 1;
        if (kt + 1 < nkt) {
            const uint32_t kd = Kb0 + (st ^ 1) * KVs;
            const uint32_t vd = Vb0 + (st ^ 1) * KVs;
            const int kn = (kt + 1) * KT;
#pragma unroll
            for (int j = 0; j < 4; j++) {
                int c = tid + j * 256;
                int row = c >> 4, seg = c & 15;
                cp16(kd + (uint32_t)(row * AR + seg * 8) * 2,
                     ksrc + (size_t)(kn + row) * 128 + seg * 8);
                const __nv_bfloat16* vs = (seg < 8)
                    ? vsrc + (size_t)row * 2 * SEQ + kn + seg * 8
                    : vsrc + (size_t)row * 2 * SEQ + SEQ + kn + (seg - 8) * 8;
                cp16(vd + (uint32_t)(row * AR + seg * 8) * 2, vs);
            }
            cp_commit();
            asm volatile("cp.async.wait_group 1;" ::: "memory");
        } else {
            asm volatile("cp.async.wait_group 0;" ::: "memory");
        }
        __syncthreads();

        const uint32_t Kb = Kb0 + st * KVs;
        const uint32_t Vb = Vb0 + st * KVs;

        // ---- S = Qaug Kaug^T (12 steps; A:[h,l,h] B:[h,h,l]) ----
        float sacc[8][4] = {};
#pragma unroll
        for (int s = 0; s < 12; s++) {
            const int s3 = s & 3;
            const int acol = (s >= 4 && s < 8) ? 64 + s3 * 16 : s3 * 16;
            const int bcol = (s < 8) ? s3 * 16 : 64 + s3 * 16;
            uint32_t af[4];
            ldm4(af, Qb + a_lane + (uint32_t)(R * AR + acol) * 2);
#pragma unroll
            for (int p = 0; p < 4; p++) {
                uint32_t bf[4];
                ldm4(bf, Kb + b_lane + (uint32_t)(p * 16 * AR + bcol) * 2);
                mma_bf16(sacc[2 * p    ], af, bf[0], bf[1]);
                mma_bf16(sacc[2 * p + 1], af, bf[2], bf[3]);
            }
        }

        // ---- causal mask (last 2 tiles) ----
        if (kt >= nkt - 2) {
            const int row0 = qt * QT + R + r4, row1 = row0 + 8;
            const int c0 = kt * KT;
#pragma unroll
            for (int na = 0; na < 8; na++) {
                const int col = c0 + na * 8 + q2;
                if (col     > row0) sacc[na][0] = -1e30f;
                if (col + 1 > row0) sacc[na][1] = -1e30f;
                if (col     > row1) sacc[na][2] = -1e30f;
                if (col + 1 > row1) sacc[na][3] = -1e30f;
            }
        }

        // ---- online softmax ----
        float tm0 = -1e30f, tm1 = -1e30f;
#pragma unroll
        for (int na = 0; na < 8; na++) {
            tm0 = fmaxf(tm0, fmaxf(sacc[na][0], sacc[na][1]));
            tm1 = fmaxf(tm1, fmaxf(sacc[na][2], sacc[na][3]));
        }
        tm0 = fmaxf(tm0, __shfl_xor_sync(0xffffffffu, tm0, 1));
        tm0 = fmaxf(tm0, __shfl_xor_sync(0xffffffffu, tm0, 2));
        tm1 = fmaxf(tm1, __shfl_xor_sync(0xffffffffu, tm1, 1));
        tm1 = fmaxf(tm1, __shfl_xor_sync(0xffffffffu, tm1, 2));
        const float mn0 = fmaxf(m0, tm0), mn1 = fmaxf(m1, tm1);
        const float fac0 = __expf(m0 - mn0), fac1 = __expf(m1 - mn1);
        m0 = mn0; m1 = mn1;
        float rs0 = 0.f, rs1 = 0.f;
#pragma unroll
        for (int na = 0; na < 8; na++) {
            sacc[na][0] = __expf(sacc[na][0] - mn0);
            sacc[na][1] = __expf(sacc[na][1] - mn0);
            sacc[na][2] = __expf(sacc[na][2] - mn1);
            sacc[na][3] = __expf(sacc[na][3] - mn1);
            rs0 += sacc[na][0] + sacc[na][1];
            rs1 += sacc[na][2] + sacc[na][3];
        }
        rs0 += __shfl_xor_sync(0xffffffffu, rs0, 1);
        rs0 += __shfl_xor_sync(0xffffffffu, rs0, 2);
        rs1 += __shfl_xor_sync(0xffffffffu, rs1, 1);
        rs1 += __shfl_xor_sync(0xffffffffu, rs1, 2);
        l0 = l0 * fac0 + rs0;
        l1 = l1 * fac1 + rs1;
#pragma unroll
        for (int na = 0; na < 8; na++) {
            oacc[na][0] *= fac0; oacc[na][1] *= fac0;
            oacc[na][2] *= fac1; oacc[na][3] *= fac1;
        }

        // ---- P split -> smem ----
#pragma unroll
        for (int na = 0; na < 8; na++) {
            const int col = na * 8 + q2;
            uint32_t hp, lp;
            split2(sacc[na][0], sacc[na][1], hp, lp);
            *(uint32_t*)&Ps[(R + r4) * AR + col]      = hp;
            *(uint32_t*)&Ps[(R + r4) * AR + 64 + col] = lp;
            split2(sacc[na][2], sacc[na][3], hp, lp);
            *(uint32_t*)&Ps[(R + r4 + 8) * AR + col]      = hp;
            *(uint32_t*)&Ps[(R + r4 + 8) * AR + 64 + col] = lp;
        }
        __syncthreads();

        // ---- O += Paug Vaug^T (12 steps) ----
#pragma unroll
        for (int s = 0; s < 12; s++) {
            const int s3 = s & 3;
            const int acol = (s >= 4 && s < 8) ? 64 + s3 * 16 : s3 * 16;
            const int bcol = (s < 8) ? s3 * 16 : 64 + s3 * 16;
            uint32_t af[4];
            ldm4(af, Pb + a_lane + (uint32_t)(R * AR + acol) * 2);
#pragma unroll
            for (int p = 0; p < 4; p++) {
                uint32_t bf[4];
                ldm4(bf, Vb + b_lane + (uint32_t)(p * 16 * AR + bcol) * 2);
                mma_bf16(oacc[2 * p    ], af, bf[0], bf[1]);
                mma_bf16(oacc[2 * p + 1], af, bf[2], bf[3]);
            }
        }
        __syncthreads();
    }

    // ---- epilogue ----
    const int b = bh / NH, h = bh % NH;
    const float inv0 = 1.f / l0, inv1 = 1.f / l1;
    const int row0 = qt * QT + R + r4;
#pragma unroll
    for (int na = 0; na < 8; na++) {
        const int col = h * HDIM + na * 8 + q2;
        *(float2*)&g_ao[((size_t)b * SEQ + row0) * DIM + col] =
            make_float2(oacc[na][0] * inv0, oacc[na][1] * inv0);
        *(float2*)&g_ao[((size_t)b * SEQ + row0 + 8) * DIM + col] =
            make_float2(oacc[na][2] * inv1, oacc[na][3] * inv1);
    }
}

// ---------------------------------------------------------------------------
// inputs: 0=q 1=k 2=v 3=attn_mask 4=Wq 5=bq 6=Wk 7=bk 8=Wv 9=bv 10=Wo 11=bo
// ---------------------------------------------------------------------------
extern "C" void kernel_launch(void* const* d_in, const int* in_sizes, int n_in,
                              void* d_out, int out_size)
{
    (void)in_sizes; (void)n_in; (void)out_size;
    const float* q  = (const float*)d_in[0];
    const float* k  = (const float*)d_in[1];
    const float* v  = (const float*)d_in[2];
    const float* Wq = (const float*)d_in[4];
    const float* bq = (const float*)d_in[5];
    const float* Wk = (const float*)d_in[6];
    const float* bk = (const float*)d_in[7];
    const float* Wv = (const float*)d_in[8];
    const float* bv = (const float*)d_in[9];
    const float* Wo = (const float*)d_in[10];
    const float* bo = (const float*)d_in[11];

    cudaFuncSetAttribute(gemm_pipe, cudaFuncAttributeMaxDynamicSharedMemorySize, GSMEM);
    cudaFuncSetAttribute(attn_mma2, cudaFuncAttributeMaxDynamicSharedMemorySize,
                         ATTN_SMEM3);

    const int XG = MTOT * (DIM / 4);   // 1048576
    const int WG = DIM * (DIM / 4);    //  262144
    const int QKG = BH * SEQ * (HDIM / 4);  // 1048576

    conv_x3<<<dim3(XG / 256, 1, 3), 256>>>(q, k, v);
    conv_w4<<<dim3(WG / 256, 1, 4), 256>>>(Wq, Wk, Wv, Wo);
    gemm_pipe<<<dim3(DIM / GBN, MTOT / GBM, 3), 256, GSMEM>>>(bq, bk, bv, nullptr, 0);

    conv_qk<<<dim3(QKG / 256, 1, 2), 256>>>();
    conv_vt<<<dim3(SEQ / 64, BH), 256>>>();

    attn_mma2<<<dim3(SEQ / QT, BH), 256, ATTN_SMEM3>>>();

    conv_ao<<<XG / 256, 256>>>();
    gemm_pipe<<<dim3(DIM / GBN, MTOT / GBM, 1), 256, GSMEM>>>(bo, bo, bo,
                                                              (float*)d_out, 1);
}

// round 17
// speedup vs baseline: 2.0523x; 1.0056x over previous
#include <cuda_runtime.h>
#include <cuda_bf16.h>
#include <cstdint>

// ---------------------------------------------------------------------------
// MultiHeadAttention: B=2, S=2048, D=1024, H=16, HD=64, causal.
// Round 17: epilogue fusion — gemm_pipe z=0/1 writes split-bf16 g_qs/g_ks
// directly (conv_qk deleted); attn epilogue writes aug-layout g_xaug directly
// (conv_ao deleted). Everything else = round-16 validated kernels.
// ---------------------------------------------------------------------------

constexpr int BB   = 2;
constexpr int SEQ  = 2048;
constexpr int DIM  = 1024;
constexpr int NH   = 16;
constexpr int HDIM = 64;
constexpr int MTOT = BB * SEQ;          // 4096
constexpr int BH   = BB * NH;           // 32
constexpr float SCALE = 0.125f;

// ---- projection GEMM ----
constexpr int KAUG = 3 * DIM;           // 3072
constexpr int GBM = 128, GBN = 128, GBK = 64;
constexpr int NKB  = KAUG / GBK;        // 48
constexpr int SPAD = 8;
constexpr int SROW = GBK + SPAD;        // 72 bf16 = 144 B
constexpr int ABUF = GBM * SROW * 2;    // 18432 B
constexpr int GSMEM = 4 * ABUF;         // 73728 B
constexpr size_t XSZ = (size_t)MTOT * KAUG;
constexpr size_t WSZ = (size_t)DIM * KAUG;

// ---- attention ----
constexpr int QT = 128;
constexpr int KT = 64;
constexpr int AR = 136;                 // smem row stride (bf16): [hi64|lo64]+pad
constexpr int ATTN_SMEM3 = 512 * AR * 2;   // 139264 B

// Scratch (__device__ globals per allocation-free rule).
__device__ float g_vh[(size_t)BH * SEQ * HDIM];
__device__ __align__(16) __nv_bfloat16 g_xaug[3 * XSZ];
__device__ __align__(16) __nv_bfloat16 g_waug[4 * WSZ];
__device__ __align__(16) __nv_bfloat16 g_qs[(size_t)BH * SEQ * 128];     // [s][hi64|lo64]
__device__ __align__(16) __nv_bfloat16 g_ks[(size_t)BH * SEQ * 128];
__device__ __align__(16) __nv_bfloat16 g_vt[(size_t)BH * HDIM * 2 * SEQ]; // [hd][S-hi|S-lo]

// ---- PTX helpers ----
__device__ __forceinline__ void mma_bf16(float* d, const uint32_t* a,
                                         uint32_t b0, uint32_t b1) {
    asm volatile("mma.sync.aligned.m16n8k16.row.col.f32.bf16.bf16.f32 "
        "{%0,%1,%2,%3}, {%4,%5,%6,%7}, {%8,%9}, {%0,%1,%2,%3};"
        : "+f"(d[0]), "+f"(d[1]), "+f"(d[2]), "+f"(d[3])
        : "r"(a[0]), "r"(a[1]), "r"(a[2]), "r"(a[3]), "r"(b0), "r"(b1));
}
__device__ __forceinline__ void ldm4(uint32_t* r, uint32_t addr) {
    asm volatile("ldmatrix.sync.aligned.m8n8.x4.shared.b16 {%0,%1,%2,%3}, [%4];"
        : "=r"(r[0]), "=r"(r[1]), "=r"(r[2]), "=r"(r[3]) : "r"(addr));
}
__device__ __forceinline__ void cp16(uint32_t smem, const void* g) {
    asm volatile("cp.async.cg.shared.global [%0], [%1], 16;" :: "r"(smem), "l"(g));
}
__device__ __forceinline__ void cp_commit() {
    asm volatile("cp.async.commit_group;" ::: "memory");
}
__device__ __forceinline__ void split2(float x, float y, uint32_t& hp, uint32_t& lp) {
    __nv_bfloat16 hx = __float2bfloat16(x), hy = __float2bfloat16(y);
    __nv_bfloat16 lx = __float2bfloat16(x - __bfloat162float(hx));
    __nv_bfloat16 ly = __float2bfloat16(y - __bfloat162float(hy));
    __nv_bfloat162 h; h.x = hx; h.y = hy; hp = *(uint32_t*)&h;
    __nv_bfloat162 l; l.x = lx; l.y = ly; lp = *(uint32_t*)&l;
}

// ============================================================================
// conv kernels for inputs (round-8, validated)
// ============================================================================
__device__ __forceinline__ void conv_row(const float* __restrict__ X,
                                         __nv_bfloat16* __restrict__ out,
                                         int i, int lo_seg)
{
    int m  = i >> 8;
    int kg = (i & 255) << 2;
    float4 v = *(const float4*)(X + (size_t)m * DIM + kg);
    uint32_t hA, lA, hB, lB;
    split2(v.x, v.y, hA, lA);
    split2(v.z, v.w, hB, lB);
    __nv_bfloat16* base = out + (size_t)m * KAUG + kg;
    *(uint32_t*)(base + 0) = hA;
    *(uint32_t*)(base + 2) = hB;
    *(uint32_t*)(base + DIM + 0)     = (lo_seg == 1) ? lA : hA;
    *(uint32_t*)(base + DIM + 2)     = (lo_seg == 1) ? lB : hB;
    *(uint32_t*)(base + 2 * DIM + 0) = (lo_seg == 2) ? lA : hA;
    *(uint32_t*)(base + 2 * DIM + 2) = (lo_seg == 2) ? lB : hB;
}

__global__ __launch_bounds__(256) void conv_x3(const float* __restrict__ x0,
                                               const float* __restrict__ x1,
                                               const float* __restrict__ x2)
{
    const int z = blockIdx.z;
    const float* X = (z == 0) ? x0 : (z == 1) ? x1 : x2;
    conv_row(X, g_xaug + (size_t)z * XSZ, blockIdx.x * 256 + threadIdx.x, 1);
}

__global__ __launch_bounds__(256) void conv_w4(const float* __restrict__ w0,
                                               const float* __restrict__ w1,
                                               const float* __restrict__ w2,
                                               const float* __restrict__ w3)
{
    const int z = blockIdx.z;
    const float* W = (z == 0) ? w0 : (z == 1) ? w1 : (z == 2) ? w2 : w3;
    conv_row(W, g_waug + (size_t)z * WSZ, blockIdx.x * 256 + threadIdx.x, 2);
}

// conv_vt: V [bh][s][hd] -> g_vt [bh][hd][S-hi | S-lo], smem-staged transpose.
__global__ __launch_bounds__(256) void conv_vt()
{
    __shared__ float tile[64][65];
    const int tid = threadIdx.x;
    const int kt = blockIdx.x, bh = blockIdx.y;
    const int wid = tid >> 5, lane = tid & 31;

    const float* src = g_vh + ((size_t)bh * SEQ + kt * 64) * HDIM;
#pragma unroll
    for (int j = 0; j < 4; j++) {
        int idx = tid + j * 256;
        int row = idx >> 4, cg = (idx & 15) << 2;
        float4 v = *(const float4*)(src + row * HDIM + cg);
        tile[row][cg + 0] = v.x; tile[row][cg + 1] = v.y;
        tile[row][cg + 2] = v.z; tile[row][cg + 3] = v.w;
    }
    __syncthreads();

#pragma unroll
    for (int r = 0; r < 8; r++) {
        const int hd = wid * 8 + r;
        const int s2 = lane * 2;
        uint32_t hp, lp;
        split2(tile[s2][hd], tile[s2 + 1][hd], hp, lp);
        __nv_bfloat16* dst = g_vt + ((size_t)bh * HDIM + hd) * 2 * SEQ;
        *(uint32_t*)(dst + kt * 64 + s2)       = hp;
        *(uint32_t*)(dst + SEQ + kt * 64 + s2) = lp;
    }
}

// ============================================================================
// Pipelined HMMA projection GEMM (round-12 core) with fused split epilogue:
// z=0 -> g_qs (SCALE folded), z=1 -> g_ks, z=2 -> g_vh fp32 (for conv_vt),
// final_mode=1 -> dense fp32 Yout.
// ============================================================================
__global__ __launch_bounds__(256, 2) void gemm_pipe(
    const float* __restrict__ b0p, const float* __restrict__ b1p,
    const float* __restrict__ b2p, float* __restrict__ Yout, int final_mode)
{
    extern __shared__ __align__(16) char smem[];
    const uint32_t sbase = (uint32_t)__cvta_generic_to_shared(smem);

    const int tid  = threadIdx.x;
    const int lane = tid & 31;
    const int wid  = tid >> 5;
    const int wm = wid >> 1;
    const int wn = wid & 1;
    const int r4 = lane >> 2;
    const int q2 = (lane & 3) << 1;
    const int z  = blockIdx.z;
    const int n0 = blockIdx.x * GBN;
    const int m0 = blockIdx.y * GBM;

    const int lr = tid >> 1;
    const int ls = (tid & 1) << 2;

    const __nv_bfloat16* ag = g_xaug + (final_mode ? 0 : (size_t)z * XSZ)
                            + (size_t)(m0 + lr) * KAUG + ls * 8;
    const __nv_bfloat16* bg = g_waug + (size_t)(final_mode ? 3 : z) * WSZ
                            + (size_t)(n0 + lr) * KAUG + ls * 8;
    const float* bias = (z == 0) ? b0p : (z == 1) ? b1p : b2p;

    const uint32_t da0 = sbase + (uint32_t)(lr * SROW + ls * 8) * 2;
    const uint32_t db0 = da0 + 2 * ABUF;

    float acc[2][8][4] = {};

    {
#pragma unroll
        for (int j = 0; j < 4; j++) {
            cp16(da0 + j * 16, ag + j * 8);
            cp16(db0 + j * 16, bg + j * 8);
        }
        cp_commit();
    }

    const uint32_t a_lane = (uint32_t)(((lane & 15)) * SROW + (lane >> 4) * 8) * 2;
    const uint32_t b_lane = (uint32_t)(((lane >> 4) * 8 + (lane & 7)) * SROW
                                       + ((lane >> 3) & 1) * 8) * 2;

    for (int kb = 0; kb < NKB; kb++) {
        const int st = kb & 1;
        if (kb + 1 < NKB) {
            const __nv_bfloat16* a = ag + (size_t)(kb + 1) * GBK;
            const __nv_bfloat16* b = bg + (size_t)(kb + 1) * GBK;
            const uint32_t da = da0 + (st ^ 1) * ABUF;
            const uint32_t db = db0 + (st ^ 1) * ABUF;
#pragma unroll
            for (int j = 0; j < 4; j++) {
                cp16(da + j * 16, a + j * 8);
                cp16(db + j * 16, b + j * 8);
            }
            cp_commit();
            asm volatile("cp.async.wait_group 1;" ::: "memory");
        } else {
            asm volatile("cp.async.wait_group 0;" ::: "memory");
        }
        __syncthreads();

        const uint32_t Ab = sbase + st * ABUF;
        const uint32_t Bb = sbase + 2 * ABUF + st * ABUF;
#pragma unroll
        for (int ka = 0; ka < 4; ka++) {
            const int k0b = ka * 16 * 2;
            uint32_t afr[2][4];
            ldm4(afr[0], Ab + a_lane + (uint32_t)(wm * 32) * SROW * 2 + k0b);
            ldm4(afr[1], Ab + a_lane + (uint32_t)(wm * 32 + 16) * SROW * 2 + k0b);
#pragma unroll
            for (int p = 0; p < 4; p++) {
                uint32_t bf[4];
                ldm4(bf, Bb + b_lane + (uint32_t)(wn * 64 + p * 16) * SROW * 2 + k0b);
                mma_bf16(acc[0][2 * p    ], afr[0], bf[0], bf[1]);
                mma_bf16(acc[1][2 * p    ], afr[1], bf[0], bf[1]);
                mma_bf16(acc[0][2 * p + 1], afr[0], bf[2], bf[3]);
                mma_bf16(acc[1][2 * p + 1], afr[1], bf[2], bf[3]);
            }
        }
        __syncthreads();
    }

    // epilogue: bias, then fused split-store per destination kind
    const float qsc = (z == 0) ? SCALE : 1.0f;
#pragma unroll
    for (int ma = 0; ma < 2; ma++) {
#pragma unroll
        for (int na = 0; na < 8; na++) {
            const int e  = n0 + wn * 64 + na * 8 + q2;
            const float2 bv = *(const float2*)(bias + e);
            const int row0 = m0 + wm * 32 + ma * 16 + r4;
#pragma unroll
            for (int h2i = 0; h2i < 2; h2i++) {
                const int m = row0 + h2i * 8;
                float2 rv = make_float2(acc[ma][na][h2i * 2 + 0] + bv.x,
                                        acc[ma][na][h2i * 2 + 1] + bv.y);
                if (final_mode) {
                    *(float2*)(Yout + (size_t)m * DIM + e) = rv;
                } else {
                    const int b = m >> 11, s = m & (SEQ - 1);
                    const int h = e >> 6, hd = e & 63;
                    if (z == 2) {
                        *(float2*)(g_vh + (((size_t)(b * NH + h) * SEQ) + s) * HDIM + hd) = rv;
                    } else {
                        __nv_bfloat16* dst = z ? g_ks : g_qs;
                        uint32_t hp, lp;
                        split2(rv.x * qsc, rv.y * qsc, hp, lp);
                        __nv_bfloat16* o = dst + ((size_t)(b * NH + h) * SEQ + s) * 128 + hd;
                        *(uint32_t*)(o)      = hp;
                        *(uint32_t*)(o + 64) = lp;
                    }
                }
            }
        }
    }
}

// ============================================================================
// HMMA flash attention v2 (round-16, validated) with fused aug-split epilogue
// writing g_xaug directly ([xh, xl, xh] activation layout).
// ============================================================================
__global__ __launch_bounds__(256) void attn_mma2()
{
    extern __shared__ __align__(16) __nv_bfloat16 sb[];
    const uint32_t sbase = (uint32_t)__cvta_generic_to_shared(sb);
    const uint32_t Qb  = sbase;                       // 128*AR
    const uint32_t Kb0 = sbase + 128 * AR * 2;        // 2 x 64*AR
    const uint32_t Vb0 = sbase + 256 * AR * 2;        // 2 x 64*AR
    const uint32_t Pb  = sbase + 384 * AR * 2;        // 128*AR
    const uint32_t KVs = 64 * AR * 2;
    __nv_bfloat16* Ps = sb + 384 * AR;

    const int tid  = threadIdx.x;
    const int wid  = tid >> 5;
    const int lane = tid & 31;
    const int r4 = lane >> 2;
    const int q2 = (lane & 3) << 1;
    const int qt = gridDim.x - 1 - blockIdx.x;        // long diagonals first
    const int bh = blockIdx.y;
    const int R  = wid * 16;
    const int nkt = 2 * qt + 2;

    const __nv_bfloat16* ksrc = g_ks + (size_t)bh * SEQ * 128;
    const __nv_bfloat16* vsrc = g_vt + (size_t)bh * HDIM * 2 * SEQ;

    // Q prefetch (whole 128x[hi|lo] tile)
    {
        const __nv_bfloat16* qsrc = g_qs + ((size_t)bh * SEQ + qt * QT) * 128;
#pragma unroll
        for (int j = 0; j < 8; j++) {
            int c = tid + j * 256;
            int row = c >> 4, seg = c & 15;
            cp16(Qb + (uint32_t)(row * AR + seg * 8) * 2, qsrc + row * 128 + seg * 8);
        }
    }
    // K/V tile 0
    {
#pragma unroll
        for (int j = 0; j < 4; j++) {
            int c = tid + j * 256;
            int row = c >> 4, seg = c & 15;
            cp16(Kb0 + (uint32_t)(row * AR + seg * 8) * 2,
                 ksrc + (size_t)row * 128 + seg * 8);
            const __nv_bfloat16* vs = (seg < 8)
                ? vsrc + (size_t)row * 2 * SEQ + seg * 8
                : vsrc + (size_t)row * 2 * SEQ + SEQ + (seg - 8) * 8;
            cp16(Vb0 + (uint32_t)(row * AR + seg * 8) * 2, vs);
        }
    }
    cp_commit();

    const uint32_t a_lane = (uint32_t)((lane & 15) * AR + (lane >> 4) * 8) * 2;
    const uint32_t b_lane = (uint32_t)(((lane >> 4) * 8 + (lane & 7)) * AR
                                       + ((lane >> 3) & 1) * 8) * 2;

    float m0 = -1e30f, m1 = -1e30f, l0 = 0.f, l1 = 0.f;
    float oacc[8][4] = {};

    for (int kt = 0; kt < nkt; kt++) {
        const int st = kt & 1;
        if (kt + 1 < nkt) {
            const uint32_t kd = Kb0 + (st ^ 1) * KVs;
            const uint32_t vd = Vb0 + (st ^ 1) * KVs;
            const int kn = (kt + 1) * KT;
#pragma unroll
            for (int j = 0; j < 4; j++) {
                int c = tid + j * 256;
                int row = c >> 4, seg = c & 15;
                cp16(kd + (uint32_t)(row * AR + seg * 8) * 2,
                     ksrc + (size_t)(kn + row) * 128 + seg * 8);
                const __nv_bfloat16* vs = (seg < 8)
                    ? vsrc + (size_t)row * 2 * SEQ + kn + seg * 8
                    : vsrc + (size_t)row * 2 * SEQ + SEQ + kn + (seg - 8) * 8;
                cp16(vd + (uint32_t)(row * AR + seg * 8) * 2, vs);
            }
            cp_commit();
            asm volatile("cp.async.wait_group 1;" ::: "memory");
        } else {
            asm volatile("cp.async.wait_group 0;" ::: "memory");
        }
        __syncthreads();

        const uint32_t Kb = Kb0 + st * KVs;
        const uint32_t Vb = Vb0 + st * KVs;

        // ---- S = Qaug Kaug^T (12 steps; A:[h,l,h] B:[h,h,l]) ----
        float sacc[8][4] = {};
#pragma unroll
        for (int s = 0; s < 12; s++) {
            const int s3 = s & 3;
            const int acol = (s >= 4 && s < 8) ? 64 + s3 * 16 : s3 * 16;
            const int bcol = (s < 8) ? s3 * 16 : 64 + s3 * 16;
            uint32_t af[4];
            ldm4(af, Qb + a_lane + (uint32_t)(R * AR + acol) * 2);
#pragma unroll
            for (int p = 0; p < 4; p++) {
                uint32_t bf[4];
                ldm4(bf, Kb + b_lane + (uint32_t)(p * 16 * AR + bcol) * 2);
                mma_bf16(sacc[2 * p    ], af, bf[0], bf[1]);
                mma_bf16(sacc[2 * p + 1], af, bf[2], bf[3]);
            }
        }

        // ---- causal mask (last 2 tiles) ----
        if (kt >= nkt - 2) {
            const int row0 = qt * QT + R + r4, row1 = row0 + 8;
            const int c0 = kt * KT;
#pragma unroll
            for (int na = 0; na < 8; na++) {
                const int col = c0 + na * 8 + q2;
                if (col     > row0) sacc[na][0] = -1e30f;
                if (col + 1 > row0) sacc[na][1] = -1e30f;
                if (col     > row1) sacc[na][2] = -1e30f;
                if (col + 1 > row1) sacc[na][3] = -1e30f;
            }
        }

        // ---- online softmax ----
        float tm0 = -1e30f, tm1 = -1e30f;
#pragma unroll
        for (int na = 0; na < 8; na++) {
            tm0 = fmaxf(tm0, fmaxf(sacc[na][0], sacc[na][1]));
            tm1 = fmaxf(tm1, fmaxf(sacc[na][2], sacc[na][3]));
        }
        tm0 = fmaxf(tm0, __shfl_xor_sync(0xffffffffu, tm0, 1));
        tm0 = fmaxf(tm0, __shfl_xor_sync(0xffffffffu, tm0, 2));
        tm1 = fmaxf(tm1, __shfl_xor_sync(0xffffffffu, tm1, 1));
        tm1 = fmaxf(tm1, __shfl_xor_sync(0xffffffffu, tm1, 2));
        const float mn0 = fmaxf(m0, tm0), mn1 = fmaxf(m1, tm1);
        const float fac0 = __expf(m0 - mn0), fac1 = __expf(m1 - mn1);
        m0 = mn0; m1 = mn1;
        float rs0 = 0.f, rs1 = 0.f;
#pragma unroll
        for (int na = 0; na < 8; na++) {
            sacc[na][0] = __expf(sacc[na][0] - mn0);
            sacc[na][1] = __expf(sacc[na][1] - mn0);
            sacc[na][2] = __expf(sacc[na][2] - mn1);
            sacc[na][3] = __expf(sacc[na][3] - mn1);
            rs0 += sacc[na][0] + sacc[na][1];
            rs1 += sacc[na][2] + sacc[na][3];
        }
        rs0 += __shfl_xor_sync(0xffffffffu, rs0, 1);
        rs0 += __shfl_xor_sync(0xffffffffu, rs0, 2);
        rs1 += __shfl_xor_sync(0xffffffffu, rs1, 1);
        rs1 += __shfl_xor_sync(0xffffffffu, rs1, 2);
        l0 = l0 * fac0 + rs0;
        l1 = l1 * fac1 + rs1;
#pragma unroll
        for (int na = 0; na < 8; na++) {
            oacc[na][0] *= fac0; oacc[na][1] *= fac0;
            oacc[na][2] *= fac1; oacc[na][3] *= fac1;
        }

        // ---- P split -> smem ----
#pragma unroll
        for (int na = 0; na < 8; na++) {
            const int col = na * 8 + q2;
            uint32_t hp, lp;
            split2(sacc[na][0], sacc[na][1], hp, lp);
            *(uint32_t*)&Ps[(R + r4) * AR + col]      = hp;
            *(uint32_t*)&Ps[(R + r4) * AR + 64 + col] = lp;
            split2(sacc[na][2], sacc[na][3], hp, lp);
            *(uint32_t*)&Ps[(R + r4 + 8) * AR + col]      = hp;
            *(uint32_t*)&Ps[(R + r4 + 8) * AR + 64 + col] = lp;
        }
        __syncthreads();

        // ---- O += Paug Vaug^T (12 steps) ----
#pragma unroll
        for (int s = 0; s < 12; s++) {
            const int s3 = s & 3;
            const int acol = (s >= 4 && s < 8) ? 64 + s3 * 16 : s3 * 16;
            const int bcol = (s < 8) ? s3 * 16 : 64 + s3 * 16;
            uint32_t af[4];
            ldm4(af, Pb + a_lane + (uint32_t)(R * AR + acol) * 2);
#pragma unroll
            for (int p = 0; p < 4; p++) {
                uint32_t bf[4];
                ldm4(bf, Vb + b_lane + (uint32_t)(p * 16 * AR + bcol) * 2);
                mma_bf16(oacc[2 * p    ], af, bf[0], bf[1]);
                mma_bf16(oacc[2 * p + 1], af, bf[2], bf[3]);
            }
        }
        __syncthreads();
    }

    // ---- fused epilogue: O/l -> g_xaug aug layout [xh, xl, xh] ----
    const int b = bh / NH, h = bh % NH;
    const float inv0 = 1.f / l0, inv1 = 1.f / l1;
    const int row0 = qt * QT + R + r4;
#pragma unroll
    for (int na = 0; na < 8; na++) {
        const int col = h * HDIM + na * 8 + q2;
        uint32_t hp, lp;
        split2(oacc[na][0] * inv0, oacc[na][1] * inv0, hp, lp);
        __nv_bfloat16* o = g_xaug + (size_t)(b * SEQ + row0) * KAUG + col;
        *(uint32_t*)(o)           = hp;
        *(uint32_t*)(o + DIM)     = lp;
        *(uint32_t*)(o + 2 * DIM) = hp;
        split2(oacc[na][2] * inv1, oacc[na][3] * inv1, hp, lp);
        o = g_xaug + (size_t)(b * SEQ + row0 + 8) * KAUG + col;
        *(uint32_t*)(o)           = hp;
        *(uint32_t*)(o + DIM)     = lp;
        *(uint32_t*)(o + 2 * DIM) = hp;
    }
}

// ---------------------------------------------------------------------------
// inputs: 0=q 1=k 2=v 3=attn_mask 4=Wq 5=bq 6=Wk 7=bk 8=Wv 9=bv 10=Wo 11=bo
// ---------------------------------------------------------------------------
extern "C" void kernel_launch(void* const* d_in, const int* in_sizes, int n_in,
                              void* d_out, int out_size)
{
    (void)in_sizes; (void)n_in; (void)out_size;
    const float* q  = (const float*)d_in[0];
    const float* k  = (const float*)d_in[1];
    const float* v  = (const float*)d_in[2];
    const float* Wq = (const float*)d_in[4];
    const float* bq = (const float*)d_in[5];
    const float* Wk = (const float*)d_in[6];
    const float* bk = (const float*)d_in[7];
    const float* Wv = (const float*)d_in[8];
    const float* bv = (const float*)d_in[9];
    const float* Wo = (const float*)d_in[10];
    const float* bo = (const float*)d_in[11];

    cudaFuncSetAttribute(gemm_pipe, cudaFuncAttributeMaxDynamicSharedMemorySize, GSMEM);
    cudaFuncSetAttribute(attn_mma2, cudaFuncAttributeMaxDynamicSharedMemorySize,
                         ATTN_SMEM3);

    const int XG = MTOT * (DIM / 4);   // 1048576
    const int WG = DIM * (DIM / 4);    //  262144

    conv_x3<<<dim3(XG / 256, 1, 3), 256>>>(q, k, v);
    conv_w4<<<dim3(WG / 256, 1, 4), 256>>>(Wq, Wk, Wv, Wo);
    gemm_pipe<<<dim3(DIM / GBN, MTOT / GBM, 3), 256, GSMEM>>>(bq, bk, bv, nullptr, 0);

    conv_vt<<<dim3(SEQ / 64, BH), 256>>>();

    attn_mma2<<<dim3(SEQ / QT, BH), 256, ATTN_SMEM3>>>();

    gemm_pipe<<<dim3(DIM / GBN, MTOT / GBM, 1), 256, GSMEM>>>(bo, bo, bo,
                                                              (float*)d_out, 1);
}